// round 1
// baseline (speedup 1.0000x reference)
#include <cuda_runtime.h>
#include <math.h>

#define B_   16
#define S_   2048
#define E_   256
#define H_   4
#define L_   2
#define NQ_  8
#define FFN_ 512
#define C_   2
#define DK_  64
#define M_   (B_*S_)   // 32768 rows

// ---------------- scratch (allocation-free rule: __device__ globals) ----------
__device__ float g_x[(size_t)M_*E_];      // 32 MB activations
__device__ float g_y[(size_t)M_*E_];      // 32 MB gemm output
__device__ float g_h[(size_t)M_*FFN_];    // 64 MB ffn hidden
__device__ float g_pp[B_*16*E_];          // pooling partials

// ---------------- embed + positional encoding --------------------------------
__global__ void k_embed(const int* __restrict__ tok, const float* __restrict__ emb) {
    int row = blockIdx.x;            // b*S + s
    int e   = threadIdx.x;           // 0..255
    int t   = tok[row];
    int s   = row & (S_ - 1);
    int i   = e >> 1;
    float freq = expf(-(float)(2 * i) * (9.210340371976184f / (float)E_));
    float ang  = (float)s * freq;
    float pe   = (e & 1) ? cosf(ang) : sinf(ang);
    g_x[(size_t)row * E_ + e] = emb[(size_t)t * E_ + e] + pe;
}

// ---------------- tiled SGEMM, N fixed = 256, optional cos(A+theta) ----------
#define BM 128
#define BN 128
#define BK 8
#define TM 8
#define TN 8

template <int AMODE>
__global__ void __launch_bounds__(256)
k_gemm(const float* __restrict__ A, const float* __restrict__ Bw,
       const float* __restrict__ bias, const float* __restrict__ theta,
       float* __restrict__ Cout, int K) {
    __shared__ float As[BK][BM];
    __shared__ float Bs[BK][BN + 4];

    int tid = threadIdx.x;
    int bm  = blockIdx.y * BM;
    int bn  = blockIdx.x * BN;
    int tm  = (tid >> 4) * TM;       // 0..120
    int tn  = (tid & 15) * TN;       // 0..120

    float acc[TM][TN];
#pragma unroll
    for (int i = 0; i < TM; i++)
#pragma unroll
        for (int j = 0; j < TN; j++) acc[i][j] = 0.f;

    int arow = tid >> 1;             // 0..127
    int acol = (tid & 1) * 4;        // 0 or 4
    int brow = tid >> 5;             // 0..7
    int bcol = (tid & 31) * 4;       // 0..124

    for (int k0 = 0; k0 < K; k0 += BK) {
        float4 av = *(const float4*)(A + (size_t)(bm + arow) * K + k0 + acol);
        if (AMODE == 1) {
            av.x = cosf(av.x + theta[(k0 + acol + 0) & 63]);
            av.y = cosf(av.y + theta[(k0 + acol + 1) & 63]);
            av.z = cosf(av.z + theta[(k0 + acol + 2) & 63]);
            av.w = cosf(av.w + theta[(k0 + acol + 3) & 63]);
        }
        As[acol + 0][arow] = av.x;
        As[acol + 1][arow] = av.y;
        As[acol + 2][arow] = av.z;
        As[acol + 3][arow] = av.w;

        float4 bv = *(const float4*)(Bw + (size_t)(k0 + brow) * E_ + bn + bcol);
        *(float4*)(&Bs[brow][bcol]) = bv;

        __syncthreads();
#pragma unroll
        for (int k = 0; k < BK; k++) {
            float ra[TM], rb[TN];
#pragma unroll
            for (int i = 0; i < TM; i++) ra[i] = As[k][tm + i];
#pragma unroll
            for (int j = 0; j < TN; j++) rb[j] = Bs[k][tn + j];
#pragma unroll
            for (int i = 0; i < TM; i++)
#pragma unroll
                for (int j = 0; j < TN; j++) acc[i][j] += ra[i] * rb[j];
        }
        __syncthreads();
    }

#pragma unroll
    for (int i = 0; i < TM; i++) {
#pragma unroll
        for (int j = 0; j < TN; j += 4) {
            float4 v;
            v.x = acc[i][j + 0] + bias[bn + tn + j + 0];
            v.y = acc[i][j + 1] + bias[bn + tn + j + 1];
            v.z = acc[i][j + 2] + bias[bn + tn + j + 2];
            v.w = acc[i][j + 3] + bias[bn + tn + j + 3];
            *(float4*)(Cout + (size_t)(bm + tm + i) * E_ + bn + tn + j) = v;
        }
    }
}

// ---------------- residual add + layernorm (one block per row, 256 thr) ------
__device__ __forceinline__ float blockSum256(float v) {
    __shared__ float sh[8];
    for (int o = 16; o > 0; o >>= 1) v += __shfl_xor_sync(0xffffffffu, v, o);
    int w = threadIdx.x >> 5;
    if ((threadIdx.x & 31) == 0) sh[w] = v;
    __syncthreads();
    if (threadIdx.x < 32) {
        float t = (threadIdx.x < 8) ? sh[threadIdx.x] : 0.f;
        for (int o = 4; o > 0; o >>= 1) t += __shfl_xor_sync(0xffffffffu, t, o);
        if (threadIdx.x == 0) sh[0] = t;
    }
    __syncthreads();
    float r = sh[0];
    __syncthreads();
    return r;
}

__global__ void k_addln(const float* __restrict__ g, const float* __restrict__ b) {
    int row = blockIdx.x;
    int e   = threadIdx.x;
    size_t idx = (size_t)row * E_ + e;
    float v = g_x[idx] + g_y[idx];
    float mean = blockSum256(v) * (1.0f / E_);
    float d = v - mean;
    float var = blockSum256(d * d) * (1.0f / E_);
    g_x[idx] = d * rsqrtf(var + 1e-5f) * g[e] + b[e];
}

// ---------------- ffn1: h = relu(cos(x[:, :8])*cos(theta) @ W1 + b1) ---------
__global__ void k_ffn1(const float* __restrict__ th, const float* __restrict__ W1,
                       const float* __restrict__ b1) {
    int row0 = blockIdx.x * 8;
    int tid  = threadIdx.x;          // 256
    __shared__ float q[8][NQ_];
    if (tid < 64) {
        int r = tid >> 3, n = tid & 7;
        q[r][n] = cosf(g_x[(size_t)(row0 + r) * E_ + n]) * cosf(th[n]);
    }
    __syncthreads();
#pragma unroll
    for (int rr = 0; rr < 2; rr++) {
        int f = tid + rr * 256;
        float w[NQ_];
#pragma unroll
        for (int n = 0; n < NQ_; n++) w[n] = W1[n * FFN_ + f];
        float bb = b1[f];
#pragma unroll
        for (int r = 0; r < 8; r++) {
            float s = bb;
#pragma unroll
            for (int n = 0; n < NQ_; n++) s += q[r][n] * w[n];
            g_h[(size_t)(row0 + r) * FFN_ + f] = fmaxf(s, 0.f);
        }
    }
}

// ---------------- mean pool (two stages) + classifier ------------------------
__global__ void k_pool() {
    int b = blockIdx.x;              // 0..15
    int c = blockIdx.y;              // 0..15 chunk of 128 rows
    int e = threadIdx.x;             // 0..255
    int base = b * S_ + c * 128;
    float s = 0.f;
#pragma unroll 4
    for (int i = 0; i < 128; i++) s += g_x[(size_t)(base + i) * E_ + e];
    g_pp[(b * 16 + c) * E_ + e] = s;
}

__global__ void k_cls(const float* __restrict__ w, const float* __restrict__ cb,
                      float* __restrict__ out) {
    int t = threadIdx.x;
    if (t < B_ * C_) {
        int b = t / C_, c = t % C_;
        float s = cb[c];
        for (int e = 0; e < E_; e++) {
            float p = 0.f;
#pragma unroll
            for (int j = 0; j < 16; j++) p += g_pp[(b * 16 + j) * E_ + e];
            s += (p * (1.0f / (float)S_)) * w[e * C_ + c];
        }
        out[b * C_ + c] = s;
    }
}

// ---------------- host launcher ----------------------------------------------
extern "C" void kernel_launch(void* const* d_in, const int* in_sizes, int n_in,
                              void* d_out, int out_size) {
    const int*   tokens     = (const int*)d_in[0];
    const float* embed      = (const float*)d_in[1];
    const float* attn_theta = (const float*)d_in[2];
    const float* combine_w  = (const float*)d_in[3];
    const float* combine_b  = (const float*)d_in[4];
    const float* ffn_theta  = (const float*)d_in[5];
    const float* lin1_w     = (const float*)d_in[6];
    const float* lin1_b     = (const float*)d_in[7];
    const float* lin2_w     = (const float*)d_in[8];
    const float* lin2_b     = (const float*)d_in[9];
    const float* ln1_g      = (const float*)d_in[10];
    const float* ln1_b      = (const float*)d_in[11];
    const float* ln2_g      = (const float*)d_in[12];
    const float* ln2_b      = (const float*)d_in[13];
    const float* cls_w      = (const float*)d_in[14];
    const float* cls_b      = (const float*)d_in[15];
    float* out = (float*)d_out;

    float *xp, *yp, *hp;
    cudaGetSymbolAddress((void**)&xp, g_x);
    cudaGetSymbolAddress((void**)&yp, g_y);
    cudaGetSymbolAddress((void**)&hp, g_h);

    k_embed<<<M_, 256>>>(tokens, embed);

    for (int l = 0; l < L_; l++) {
        // attn: y = cos(x + tile(theta)) @ combine_w + combine_b
        k_gemm<1><<<dim3(E_ / BN, M_ / BM), 256>>>(
            xp, combine_w + (size_t)l * E_ * E_, combine_b + l * E_,
            attn_theta + l * DK_, yp, E_);
        k_addln<<<M_, 256>>>(ln1_g + l * E_, ln1_b + l * E_);

        // ffn
        k_ffn1<<<M_ / 8, 256>>>(ffn_theta + l * NQ_,
                                lin1_w + (size_t)l * NQ_ * FFN_,
                                lin1_b + l * FFN_);
        k_gemm<0><<<dim3(E_ / BN, M_ / BM), 256>>>(
            hp, lin2_w + (size_t)l * FFN_ * E_, lin2_b + l * E_,
            nullptr, yp, FFN_);
        k_addln<<<M_, 256>>>(ln2_g + l * E_, ln2_b + l * E_);
    }

    k_pool<<<dim3(B_, 16), 256>>>();
    k_cls<<<1, 32>>>(cls_w, cls_b, out);
}

// round 3
// speedup vs baseline: 1.5561x; 1.5561x over previous
#include <cuda_runtime.h>
#include <cuda_bf16.h>
#include <cstdint>
#include <math.h>

#define B_   16
#define S_   2048
#define E_   256
#define L_   2
#define NQ_  8
#define FFN_ 512
#define C_   2
#define DK_  64
#define M_   (B_*S_)   // 32768 rows

// ---------------- scratch (__device__ globals; no allocations) ---------------
__device__ float g_x[(size_t)M_*E_];                             // 32 MB
__device__ float g_y[(size_t)M_*E_];                             // 32 MB
__device__ __align__(128) __nv_bfloat16 g_ahi[(size_t)M_*FFN_];  // 32 MB
__device__ __align__(128) __nv_bfloat16 g_alo[(size_t)M_*FFN_];  // 32 MB
__device__ __align__(128) __nv_bfloat16 g_whi[4*256*512];        // Wt[n][k] hi
__device__ __align__(128) __nv_bfloat16 g_wlo[4*256*512];        // Wt[n][k] lo
__device__ float g_pp[B_*16*E_];

// ---------------- PTX helpers (all plain sm_80+ features) --------------------
__device__ __forceinline__ uint32_t s2u(const void* p) {
    uint32_t a;
    asm("{ .reg .u64 t; cvta.to.shared.u64 t, %1; cvt.u32.u64 %0, t; }"
        : "=r"(a) : "l"(p));
    return a;
}
__device__ __forceinline__ void cp16(uint32_t dst, const void* src) {
    asm volatile("cp.async.cg.shared.global [%0], [%1], 16;" :: "r"(dst), "l"(src));
}
__device__ __forceinline__ void cp_commit() {
    asm volatile("cp.async.commit_group;" ::: "memory");
}
__device__ __forceinline__ void cp_wait1() {
    asm volatile("cp.async.wait_group 1;" ::: "memory");
}
__device__ __forceinline__ void cp_wait0() {
    asm volatile("cp.async.wait_group 0;" ::: "memory");
}
__device__ __forceinline__ void ldm_x4(uint32_t& r0, uint32_t& r1, uint32_t& r2,
                                       uint32_t& r3, uint32_t addr) {
    asm volatile("ldmatrix.sync.aligned.m8n8.x4.shared.b16 {%0,%1,%2,%3}, [%4];"
                 : "=r"(r0), "=r"(r1), "=r"(r2), "=r"(r3) : "r"(addr));
}
__device__ __forceinline__ void ldm_x2(uint32_t& r0, uint32_t& r1, uint32_t addr) {
    asm volatile("ldmatrix.sync.aligned.m8n8.x2.shared.b16 {%0,%1}, [%2];"
                 : "=r"(r0), "=r"(r1) : "r"(addr));
}
__device__ __forceinline__ void mma16816(float* c, uint32_t a0, uint32_t a1,
                                         uint32_t a2, uint32_t a3,
                                         uint32_t b0, uint32_t b1) {
    asm volatile(
        "mma.sync.aligned.m16n8k16.row.col.f32.bf16.bf16.f32 "
        "{%0,%1,%2,%3}, {%4,%5,%6,%7}, {%8,%9}, {%0,%1,%2,%3};"
        : "+f"(c[0]), "+f"(c[1]), "+f"(c[2]), "+f"(c[3])
        : "r"(a0), "r"(a1), "r"(a2), "r"(a3), "r"(b0), "r"(b1));
}

// ---------------- embed + positional encoding --------------------------------
__global__ void k_embed(const int* __restrict__ tok, const float* __restrict__ emb) {
    int row = blockIdx.x;
    int e   = threadIdx.x;
    int t   = tok[row];
    int s   = row & (S_ - 1);
    int i   = e >> 1;
    float freq = expf(-(float)(2 * i) * (9.210340371976184f / (float)E_));
    float ang  = (float)s * freq;
    float pe   = (e & 1) ? cosf(ang) : sinf(ang);
    g_x[(size_t)row * E_ + e] = emb[(size_t)t * E_ + e] + pe;
}

// ---------------- weight convert + transpose: W[k][n] -> Wt[n][k] hi/lo ------
__global__ void k_convw(const float* __restrict__ cw, const float* __restrict__ l2w) {
    int slot = blockIdx.y;               // 0,1: combine (K=256); 2,3: lin2 (K=512)
    int n    = blockIdx.x;
    int K    = (slot < 2) ? 256 : 512;
    const float* src = (slot < 2) ? (cw + (size_t)slot * E_ * E_)
                                  : (l2w + (size_t)(slot - 2) * FFN_ * E_);
    for (int k = threadIdx.x; k < K; k += 256) {
        float w = src[(size_t)k * E_ + n];
        __nv_bfloat16 hi = __float2bfloat16(w);
        float lo = w - __bfloat162float(hi);
        size_t o = (size_t)slot * 131072 + (size_t)n * K + k;
        g_whi[o] = hi;
        g_wlo[o] = __float2bfloat16(lo);
    }
}

// ---------------- attn A prep: a = cos(x + tile(theta)) -> bf16 hi/lo --------
__global__ void k_prep(const float* __restrict__ th) {
    size_t idx = (size_t)blockIdx.x * 256 + threadIdx.x;
    int e = threadIdx.x;
    float v = cosf(g_x[idx] + th[e & 63]);
    __nv_bfloat16 hi = __float2bfloat16(v);
    g_ahi[idx] = hi;
    g_alo[idx] = __float2bfloat16(v - __bfloat162float(hi));
}

// ---------------- HMMA bf16 split-precision GEMM -----------------------------
// Y[m][n] = sum_k A[m][k]*Wt[n][k] + bias[n];  BM=128, BN=128, BK=32, 8 warps
#define PADH  40                    // padded halves per smem row
#define ROWB  80                    // bytes per smem row
#define ABYTES (128*ROWB)           // 10240 per tile
#define BUFB   (2*ABYTES)           // A + B per buffer

__global__ void __launch_bounds__(256)
k_gemm_mma(const __nv_bfloat16* __restrict__ Ahi, const __nv_bfloat16* __restrict__ Alo,
           const __nv_bfloat16* __restrict__ Whi, const __nv_bfloat16* __restrict__ Wlo,
           const float* __restrict__ bias, float* __restrict__ Y, int K) {
    __shared__ __align__(128) char smem[2 * BUFB];   // 40 KB
    uint32_t sb = s2u(smem);

    int tid  = threadIdx.x;
    int lane = tid & 31;
    int wid  = tid >> 5;
    int m_w  = (wid >> 2) * 64;      // warp row offset (2 warps along M)
    int n_w  = (wid & 3) * 32;       // warp col offset (4 warps along N)
    size_t bm = (size_t)blockIdx.y * 128;
    size_t bn = (size_t)blockIdx.x * 128;

    const __nv_bfloat16* Ap[3] = {Ahi, Alo, Ahi};
    const __nv_bfloat16* Wp[3] = {Whi, Whi, Wlo};

    float acc[4][4][4];
#pragma unroll
    for (int i = 0; i < 4; i++)
#pragma unroll
        for (int j = 0; j < 4; j++)
#pragma unroll
            for (int c = 0; c < 4; c++) acc[i][j][c] = 0.f;

    int part = tid & 3;              // 16B chunk within 64B row
    int rbase = tid >> 2;            // 0..63

    int kc = K >> 5;                 // 32-half chunks per term
    int chunks = 3 * kc;
    int lt = 0, lk = 0;              // next chunk to load

    // prologue: load chunk 0 into buffer 0
    {
        const __nv_bfloat16* Ag = Ap[0];
        const __nv_bfloat16* Wg = Wp[0];
#pragma unroll
        for (int i = 0; i < 2; i++) {
            int r = rbase + i * 64;
            cp16(sb + r * ROWB + part * 16,
                 Ag + (bm + r) * (size_t)K + part * 8);
            cp16(sb + ABYTES + r * ROWB + part * 16,
                 Wg + (size_t)(bn + r) * K + part * 8);
        }
        cp_commit();
        lk = 32; if (lk == K) { lk = 0; lt = 1; }
    }

    for (int cc = 0; cc < chunks; cc++) {
        int buf = cc & 1;
        if (cc + 1 < chunks) {
            uint32_t db = sb + ((cc + 1) & 1) * BUFB;
            const __nv_bfloat16* Ag = Ap[lt];
            const __nv_bfloat16* Wg = Wp[lt];
#pragma unroll
            for (int i = 0; i < 2; i++) {
                int r = rbase + i * 64;
                cp16(db + r * ROWB + part * 16,
                     Ag + (bm + r) * (size_t)K + lk + part * 8);
                cp16(db + ABYTES + r * ROWB + part * 16,
                     Wg + (size_t)(bn + r) * K + lk + part * 8);
            }
            cp_commit();
            lk += 32; if (lk == K) { lk = 0; lt++; }
            cp_wait1();
        } else {
            cp_wait0();
        }
        __syncthreads();

        uint32_t aB = sb + buf * BUFB;
        uint32_t bB = aB + ABYTES;
        uint32_t aAddr = aB + (m_w + (lane & 15)) * ROWB + (lane >> 4) * 16;
        uint32_t bAddr = bB + (n_w + (lane & 7)) * ROWB + ((lane >> 3) & 1) * 16;

#pragma unroll
        for (int kb = 0; kb < 2; kb++) {          // two k16 steps per chunk
            uint32_t koff = kb * 32;              // 16 halves = 32 bytes
            uint32_t a0[4], a1[4], a2[4], a3[4];
#pragma unroll
            for (int mi = 0; mi < 4; mi++)
                ldm_x4(a0[mi], a1[mi], a2[mi], a3[mi],
                       aAddr + mi * 16 * ROWB + koff);
            uint32_t b0[4], b1[4];
#pragma unroll
            for (int ni = 0; ni < 4; ni++)
                ldm_x2(b0[ni], b1[ni], bAddr + ni * 8 * ROWB + koff);
#pragma unroll
            for (int mi = 0; mi < 4; mi++)
#pragma unroll
                for (int ni = 0; ni < 4; ni++)
                    mma16816(acc[mi][ni], a0[mi], a1[mi], a2[mi], a3[mi],
                             b0[ni], b1[ni]);
        }
        __syncthreads();
    }

    // epilogue: bias + direct float2 stores
#pragma unroll
    for (int ni = 0; ni < 4; ni++) {
        int col = (int)bn + n_w + ni * 8 + 2 * (lane & 3);
        float bc0 = bias[col], bc1 = bias[col + 1];
#pragma unroll
        for (int mi = 0; mi < 4; mi++) {
            size_t row = bm + m_w + mi * 16 + (lane >> 2);
            float2 v0 = make_float2(acc[mi][ni][0] + bc0, acc[mi][ni][1] + bc1);
            *(float2*)(Y + row * E_ + col) = v0;
            float2 v1 = make_float2(acc[mi][ni][2] + bc0, acc[mi][ni][3] + bc1);
            *(float2*)(Y + (row + 8) * E_ + col) = v1;
        }
    }
}

// ---------------- residual add + layernorm -----------------------------------
__device__ __forceinline__ float blockSum256(float v) {
    __shared__ float sh[8];
    for (int o = 16; o > 0; o >>= 1) v += __shfl_xor_sync(0xffffffffu, v, o);
    int w = threadIdx.x >> 5;
    if ((threadIdx.x & 31) == 0) sh[w] = v;
    __syncthreads();
    if (threadIdx.x < 32) {
        float t = (threadIdx.x < 8) ? sh[threadIdx.x] : 0.f;
        for (int o = 4; o > 0; o >>= 1) t += __shfl_xor_sync(0xffffffffu, t, o);
        if (threadIdx.x == 0) sh[0] = t;
    }
    __syncthreads();
    float r = sh[0];
    __syncthreads();
    return r;
}

__global__ void k_addln(const float* __restrict__ g, const float* __restrict__ b) {
    int row = blockIdx.x;
    int e   = threadIdx.x;
    size_t idx = (size_t)row * E_ + e;
    float v = g_x[idx] + g_y[idx];
    float mean = blockSum256(v) * (1.0f / E_);
    float d = v - mean;
    float var = blockSum256(d * d) * (1.0f / E_);
    g_x[idx] = d * rsqrtf(var + 1e-5f) * g[e] + b[e];
}

// ---------------- ffn1 -> bf16 hi/lo -----------------------------------------
__global__ void k_ffn1(const float* __restrict__ th, const float* __restrict__ W1,
                       const float* __restrict__ b1) {
    int row0 = blockIdx.x * 8;
    int tid  = threadIdx.x;
    __shared__ float q[8][NQ_];
    if (tid < 64) {
        int r = tid >> 3, n = tid & 7;
        q[r][n] = cosf(g_x[(size_t)(row0 + r) * E_ + n]) * cosf(th[n]);
    }
    __syncthreads();
#pragma unroll
    for (int rr = 0; rr < 2; rr++) {
        int f = tid + rr * 256;
        float w[NQ_];
#pragma unroll
        for (int n = 0; n < NQ_; n++) w[n] = W1[n * FFN_ + f];
        float bb = b1[f];
#pragma unroll
        for (int r = 0; r < 8; r++) {
            float s = bb;
#pragma unroll
            for (int n = 0; n < NQ_; n++) s += q[r][n] * w[n];
            float h = fmaxf(s, 0.f);
            __nv_bfloat16 hi = __float2bfloat16(h);
            size_t o = (size_t)(row0 + r) * FFN_ + f;
            g_ahi[o] = hi;
            g_alo[o] = __float2bfloat16(h - __bfloat162float(hi));
        }
    }
}

// ---------------- mean pool + classifier -------------------------------------
__global__ void k_pool() {
    int b = blockIdx.x;
    int c = blockIdx.y;
    int e = threadIdx.x;
    int base = b * S_ + c * 128;
    float s = 0.f;
#pragma unroll 4
    for (int i = 0; i < 128; i++) s += g_x[(size_t)(base + i) * E_ + e];
    g_pp[(b * 16 + c) * E_ + e] = s;
}

__global__ void k_cls(const float* __restrict__ w, const float* __restrict__ cb,
                      float* __restrict__ out) {
    int t = threadIdx.x;
    if (t < B_ * C_) {
        int b = t / C_, c = t % C_;
        float s = cb[c];
        for (int e = 0; e < E_; e++) {
            float p = 0.f;
#pragma unroll
            for (int j = 0; j < 16; j++) p += g_pp[(b * 16 + j) * E_ + e];
            s += (p * (1.0f / (float)S_)) * w[e * C_ + c];
        }
        out[b * C_ + c] = s;
    }
}

// ---------------- host launcher ----------------------------------------------
extern "C" void kernel_launch(void* const* d_in, const int* in_sizes, int n_in,
                              void* d_out, int out_size) {
    const int*   tokens     = (const int*)d_in[0];
    const float* embed      = (const float*)d_in[1];
    const float* attn_theta = (const float*)d_in[2];
    const float* combine_w  = (const float*)d_in[3];
    const float* combine_b  = (const float*)d_in[4];
    const float* ffn_theta  = (const float*)d_in[5];
    const float* lin1_w     = (const float*)d_in[6];
    const float* lin1_b     = (const float*)d_in[7];
    const float* lin2_w     = (const float*)d_in[8];
    const float* lin2_b     = (const float*)d_in[9];
    const float* ln1_g      = (const float*)d_in[10];
    const float* ln1_b      = (const float*)d_in[11];
    const float* ln2_g      = (const float*)d_in[12];
    const float* ln2_b      = (const float*)d_in[13];
    const float* cls_w      = (const float*)d_in[14];
    const float* cls_b      = (const float*)d_in[15];
    float* out = (float*)d_out;

    float *yp;
    __nv_bfloat16 *ahi, *alo, *whi, *wlo;
    cudaGetSymbolAddress((void**)&yp,  g_y);
    cudaGetSymbolAddress((void**)&ahi, g_ahi);
    cudaGetSymbolAddress((void**)&alo, g_alo);
    cudaGetSymbolAddress((void**)&whi, g_whi);
    cudaGetSymbolAddress((void**)&wlo, g_wlo);

    k_embed<<<M_, 256>>>(tokens, embed);
    k_convw<<<dim3(256, 4), 256>>>(combine_w, lin2_w);

    for (int l = 0; l < L_; l++) {
        k_prep<<<M_, 256>>>(attn_theta + l * DK_);
        k_gemm_mma<<<dim3(2, 256), 256>>>(
            ahi, alo, whi + (size_t)l * 131072, wlo + (size_t)l * 131072,
            combine_b + l * E_, yp, 256);
        k_addln<<<M_, 256>>>(ln1_g + l * E_, ln1_b + l * E_);

        k_ffn1<<<M_ / 8, 256>>>(ffn_theta + l * NQ_,
                                lin1_w + (size_t)l * NQ_ * FFN_,
                                lin1_b + l * FFN_);
        k_gemm_mma<<<dim3(2, 256), 256>>>(
            ahi, alo, whi + (size_t)(2 + l) * 131072, wlo + (size_t)(2 + l) * 131072,
            lin2_b + l * E_, yp, 512);
        k_addln<<<M_, 256>>>(ln2_g + l * E_, ln2_b + l * E_);
    }

    k_pool<<<dim3(B_, 16), 256>>>();
    k_cls<<<1, 32>>>(cls_w, cls_b, out);
}

// round 4
// speedup vs baseline: 1.8148x; 1.1663x over previous
#include <cuda_runtime.h>
#include <cuda_bf16.h>
#include <cstdint>
#include <math.h>

#define B_   16
#define S_   2048
#define E_   256
#define L_   2
#define NQ_  8
#define FFN_ 512
#define C_   2
#define M_   (B_*S_)   // 32768 rows

// ---------------- scratch (__device__ globals; no allocations) ---------------
__device__ float g_x[(size_t)M_*E_];                             // 32 MB
__device__ __align__(128) __nv_bfloat16 g_ahi[(size_t)M_*E_];    // 16 MB attn A hi
__device__ __align__(128) __nv_bfloat16 g_alo[(size_t)M_*E_];    // 16 MB attn A lo
__device__ __align__(128) __nv_bfloat16 g_hhi[(size_t)M_*FFN_];  // 32 MB ffn h hi
__device__ __align__(128) __nv_bfloat16 g_hlo[(size_t)M_*FFN_];  // 32 MB ffn h lo
__device__ __align__(128) __nv_bfloat16 g_whi[4*256*512];        // Wt[n][k] hi
__device__ __align__(128) __nv_bfloat16 g_wlo[4*256*512];        // Wt[n][k] lo
__device__ float g_pp[B_*16*E_];

// ---------------- PTX helpers (plain sm_80+ features) ------------------------
__device__ __forceinline__ uint32_t s2u(const void* p) {
    uint32_t a;
    asm("{ .reg .u64 t; cvta.to.shared.u64 t, %1; cvt.u32.u64 %0, t; }"
        : "=r"(a) : "l"(p));
    return a;
}
__device__ __forceinline__ void cp16(uint32_t dst, const void* src) {
    asm volatile("cp.async.cg.shared.global [%0], [%1], 16;" :: "r"(dst), "l"(src));
}
__device__ __forceinline__ void cp_commit() {
    asm volatile("cp.async.commit_group;" ::: "memory");
}
__device__ __forceinline__ void cp_wait1() {
    asm volatile("cp.async.wait_group 1;" ::: "memory");
}
__device__ __forceinline__ void cp_wait0() {
    asm volatile("cp.async.wait_group 0;" ::: "memory");
}
__device__ __forceinline__ void ldm_x4(uint32_t& r0, uint32_t& r1, uint32_t& r2,
                                       uint32_t& r3, uint32_t addr) {
    asm volatile("ldmatrix.sync.aligned.m8n8.x4.shared.b16 {%0,%1,%2,%3}, [%4];"
                 : "=r"(r0), "=r"(r1), "=r"(r2), "=r"(r3) : "r"(addr));
}
__device__ __forceinline__ void ldm_x2(uint32_t& r0, uint32_t& r1, uint32_t addr) {
    asm volatile("ldmatrix.sync.aligned.m8n8.x2.shared.b16 {%0,%1}, [%2];"
                 : "=r"(r0), "=r"(r1) : "r"(addr));
}
__device__ __forceinline__ void mma16816(float* c, uint32_t a0, uint32_t a1,
                                         uint32_t a2, uint32_t a3,
                                         uint32_t b0, uint32_t b1) {
    asm volatile(
        "mma.sync.aligned.m16n8k16.row.col.f32.bf16.bf16.f32 "
        "{%0,%1,%2,%3}, {%4,%5,%6,%7}, {%8,%9}, {%0,%1,%2,%3};"
        : "+f"(c[0]), "+f"(c[1]), "+f"(c[2]), "+f"(c[3])
        : "r"(a0), "r"(a1), "r"(a2), "r"(a3), "r"(b0), "r"(b1));
}

// ---------------- embed + PE + fused prep for layer-0 attn -------------------
__global__ void k_embed(const int* __restrict__ tok, const float* __restrict__ emb,
                        const float* __restrict__ th) {
    int row = blockIdx.x;
    int e   = threadIdx.x;
    int t   = tok[row];
    int s   = row & (S_ - 1);
    int i   = e >> 1;
    float freq = expf(-(float)(2 * i) * (9.210340371976184f / (float)E_));
    float ang  = (float)s * freq;
    float pe   = (e & 1) ? cosf(ang) : sinf(ang);
    size_t idx = (size_t)row * E_ + e;
    float x = emb[(size_t)t * E_ + e] + pe;
    g_x[idx] = x;
    float a = cosf(x + th[e & 63]);
    __nv_bfloat16 hi = __float2bfloat16(a);
    g_ahi[idx] = hi;
    g_alo[idx] = __float2bfloat16(a - __bfloat162float(hi));
}

// ---------------- weight convert + transpose ---------------------------------
__global__ void k_convw(const float* __restrict__ cw, const float* __restrict__ l2w) {
    int slot = blockIdx.y;               // 0,1: combine (K=256); 2,3: lin2 (K=512)
    int n    = blockIdx.x;
    int K    = (slot < 2) ? 256 : 512;
    const float* src = (slot < 2) ? (cw + (size_t)slot * E_ * E_)
                                  : (l2w + (size_t)(slot - 2) * FFN_ * E_);
    for (int k = threadIdx.x; k < K; k += 256) {
        float w = src[(size_t)k * E_ + n];
        __nv_bfloat16 hi = __float2bfloat16(w);
        float lo = w - __bfloat162float(hi);
        size_t o = (size_t)slot * 131072 + (size_t)n * K + k;
        g_whi[o] = hi;
        g_wlo[o] = __float2bfloat16(lo);
    }
}

// ---------------- fused GEMM + residual + LayerNorm + producer ---------------
// BM=64, BN=256(full E), BK=32, 8 warps (2M x 4N), 3-stage cp.async pipeline.
// MODE 0: attn GEMM -> LN1 -> also run ffn1, write h hi/lo (g_hhi/g_hlo)
// MODE 1: ffn GEMM  -> LN2 -> also write cos(x+thetaNext) hi/lo (g_ahi/g_alo)
// MODE 2: ffn GEMM  -> LN2 only
#define ROWB 80
#define STG  25600           // A 64*80 + B 256*80

template <int K, int MODE>
__global__ void __launch_bounds__(256, 2)
k_gf(const __nv_bfloat16* __restrict__ Ahi, const __nv_bfloat16* __restrict__ Alo,
     const __nv_bfloat16* __restrict__ Whi, const __nv_bfloat16* __restrict__ Wlo,
     const float* __restrict__ bias,
     const float* __restrict__ lnG, const float* __restrict__ lnB,
     const float* __restrict__ thN,                    // MODE 1
     const float* __restrict__ fTh, const float* __restrict__ W1,
     const float* __restrict__ b1) {                   // MODE 0
    constexpr int KC = K >> 5;
    constexpr int CH = 3 * KC;
    extern __shared__ __align__(16) char smem[];
    uint32_t sb = s2u(smem);
    int tid = threadIdx.x, lane = tid & 31, wid = tid >> 5;
    int wm = wid >> 2, wn = wid & 3;
    size_t bm = (size_t)blockIdx.x * 64;

    float acc[2][8][4];
#pragma unroll
    for (int i = 0; i < 2; i++)
#pragma unroll
        for (int j = 0; j < 8; j++)
#pragma unroll
            for (int c = 0; c < 4; c++) acc[i][j][c] = 0.f;

    int part = tid & 3, rb = tid >> 2;

    auto load_stage = [&](int st, int chunk) {
        uint32_t dst = sb + st * STG;
        int term = chunk / KC;
        int kk = (chunk - term * KC) << 5;
        const __nv_bfloat16* A = (term == 1) ? Alo : Ahi;
        const __nv_bfloat16* W = (term == 2) ? Wlo : Whi;
        cp16(dst + (uint32_t)rb * ROWB + part * 16,
             A + (bm + rb) * (size_t)K + kk + part * 8);
        uint32_t bdst = dst + 64 * ROWB;
        const __nv_bfloat16* Wb = W + (size_t)rb * K + kk + part * 8;
#pragma unroll
        for (int i = 0; i < 4; i++)
            cp16(bdst + (uint32_t)(rb + i * 64) * ROWB + part * 16,
                 Wb + (size_t)i * 64 * K);
        cp_commit();
    };

    load_stage(0, 0);
    load_stage(1, 1);

    for (int cc = 0; cc < CH; cc++) {
        if (cc + 1 < CH) cp_wait1(); else cp_wait0();
        __syncthreads();
        if (cc + 2 < CH) load_stage((cc + 2) % 3, cc + 2);

        uint32_t aB = sb + (cc % 3) * STG;
        uint32_t bB = aB + 64 * ROWB;
        uint32_t aAddr = aB + (wm * 32 + (lane & 15)) * ROWB + (lane >> 4) * 16;
        uint32_t bAddr = bB + (wn * 64 + (lane & 7)) * ROWB + ((lane >> 3) & 1) * 16;

#pragma unroll
        for (int kb = 0; kb < 2; kb++) {
            uint32_t ko = kb * 32;
            uint32_t a0[2], a1[2], a2[2], a3[2];
#pragma unroll
            for (int mi = 0; mi < 2; mi++)
                ldm_x4(a0[mi], a1[mi], a2[mi], a3[mi], aAddr + mi * 16 * ROWB + ko);
            uint32_t b0[8], b1[8];
#pragma unroll
            for (int ni = 0; ni < 8; ni++)
                ldm_x2(b0[ni], b1[ni], bAddr + ni * 8 * ROWB + ko);
#pragma unroll
            for (int mi = 0; mi < 2; mi++)
#pragma unroll
                for (int ni = 0; ni < 8; ni++)
                    mma16816(acc[mi][ni], a0[mi], a1[mi], a2[mi], a3[mi],
                             b0[ni], b1[ni]);
        }
    }
    __syncthreads();

    // ---------- epilogue: resid + LN (+ producers) ----------
    float2* red = (float2*)smem;            // [64][4] (sum, sumsq)
    float2* mr  = ((float2*)smem) + 256;    // [64]    (mean, rstd)
    float*  qsh = (float*)(((float2*)smem) + 320);  // [64][8]

    int mcol = wn * 64 + (lane & 3) * 2;
    int r0l  = wm * 32 + (lane >> 2);

#pragma unroll
    for (int mi = 0; mi < 2; mi++) {
        float s0 = 0, q0 = 0, s1 = 0, q1 = 0;
        size_t ra = bm + r0l + mi * 16;
#pragma unroll
        for (int ni = 0; ni < 8; ni++) {
            int col = mcol + ni * 8;
            float2 x0 = *(const float2*)(g_x + ra * E_ + col);
            float2 x1 = *(const float2*)(g_x + (ra + 8) * E_ + col);
            float bcx = bias[col], bcy = bias[col + 1];
            float v0 = acc[mi][ni][0] + bcx + x0.x;
            float v1 = acc[mi][ni][1] + bcy + x0.y;
            float v2 = acc[mi][ni][2] + bcx + x1.x;
            float v3 = acc[mi][ni][3] + bcy + x1.y;
            acc[mi][ni][0] = v0; acc[mi][ni][1] = v1;
            acc[mi][ni][2] = v2; acc[mi][ni][3] = v3;
            s0 += v0 + v1; q0 += v0 * v0 + v1 * v1;
            s1 += v2 + v3; q1 += v2 * v2 + v3 * v3;
        }
#pragma unroll
        for (int o = 1; o <= 2; o <<= 1) {
            s0 += __shfl_xor_sync(0xffffffffu, s0, o);
            q0 += __shfl_xor_sync(0xffffffffu, q0, o);
            s1 += __shfl_xor_sync(0xffffffffu, s1, o);
            q1 += __shfl_xor_sync(0xffffffffu, q1, o);
        }
        if ((lane & 3) == 0) {
            int rl = r0l + mi * 16;
            red[rl * 4 + wn] = make_float2(s0, q0);
            red[(rl + 8) * 4 + wn] = make_float2(s1, q1);
        }
    }
    __syncthreads();
    if (tid < 64) {
        float s = 0, q = 0;
#pragma unroll
        for (int j = 0; j < 4; j++) { float2 t = red[tid * 4 + j]; s += t.x; q += t.y; }
        float mean = s * (1.0f / E_);
        float var  = q * (1.0f / E_) - mean * mean;
        mr[tid] = make_float2(mean, rsqrtf(var + 1e-5f));
    }
    __syncthreads();

#pragma unroll
    for (int mi = 0; mi < 2; mi++) {
        int rl = r0l + mi * 16;
        float2 m0 = mr[rl], m1 = mr[rl + 8];
        size_t ra = bm + rl;
#pragma unroll
        for (int ni = 0; ni < 8; ni++) {
            int col = mcol + ni * 8;
            float gx = lnG[col], gy = lnG[col + 1];
            float bx = lnB[col], by = lnB[col + 1];
            float o0 = (acc[mi][ni][0] - m0.x) * m0.y * gx + bx;
            float o1 = (acc[mi][ni][1] - m0.x) * m0.y * gy + by;
            float o2 = (acc[mi][ni][2] - m1.x) * m1.y * gx + bx;
            float o3 = (acc[mi][ni][3] - m1.x) * m1.y * gy + by;
            *(float2*)(g_x + ra * E_ + col) = make_float2(o0, o1);
            *(float2*)(g_x + (ra + 8) * E_ + col) = make_float2(o2, o3);
            if constexpr (MODE == 1) {
                float t0 = thN[col & 63], t1 = thN[(col + 1) & 63];
                float a0 = cosf(o0 + t0), a1 = cosf(o1 + t1);
                float a2 = cosf(o2 + t0), a3 = cosf(o3 + t1);
                __nv_bfloat16 h0 = __float2bfloat16(a0), h1 = __float2bfloat16(a1);
                __nv_bfloat16 h2 = __float2bfloat16(a2), h3 = __float2bfloat16(a3);
                *(__nv_bfloat162*)(g_ahi + ra * E_ + col) = __halves2bfloat162(h0, h1);
                *(__nv_bfloat162*)(g_ahi + (ra + 8) * E_ + col) = __halves2bfloat162(h2, h3);
                *(__nv_bfloat162*)(g_alo + ra * E_ + col) =
                    __halves2bfloat162(__float2bfloat16(a0 - __bfloat162float(h0)),
                                       __float2bfloat16(a1 - __bfloat162float(h1)));
                *(__nv_bfloat162*)(g_alo + (ra + 8) * E_ + col) =
                    __halves2bfloat162(__float2bfloat16(a2 - __bfloat162float(h2)),
                                       __float2bfloat16(a3 - __bfloat162float(h3)));
            }
            if constexpr (MODE == 0) {
                if (wn == 0 && ni == 0) {
                    int c = (lane & 3) * 2;
                    qsh[rl * 8 + c]       = cosf(o0) * cosf(fTh[c]);
                    qsh[rl * 8 + c + 1]   = cosf(o1) * cosf(fTh[c + 1]);
                    qsh[(rl + 8) * 8 + c]     = cosf(o2) * cosf(fTh[c]);
                    qsh[(rl + 8) * 8 + c + 1] = cosf(o3) * cosf(fTh[c + 1]);
                }
            }
        }
    }

    if constexpr (MODE == 0) {
        __syncthreads();
        int f = tid * 2;
        float w0[8], w1[8];
#pragma unroll
        for (int n = 0; n < 8; n++) {
            w0[n] = W1[n * FFN_ + f];
            w1[n] = W1[n * FFN_ + f + 1];
        }
        float bb0 = b1[f], bb1 = b1[f + 1];
        for (int r = 0; r < 64; r++) {
            float h0 = bb0, h1 = bb1;
#pragma unroll
            for (int n = 0; n < 8; n++) {
                float qv = qsh[r * 8 + n];
                h0 += qv * w0[n];
                h1 += qv * w1[n];
            }
            h0 = fmaxf(h0, 0.f); h1 = fmaxf(h1, 0.f);
            __nv_bfloat16 p0 = __float2bfloat16(h0), p1 = __float2bfloat16(h1);
            __nv_bfloat16 l0 = __float2bfloat16(h0 - __bfloat162float(p0));
            __nv_bfloat16 l1 = __float2bfloat16(h1 - __bfloat162float(p1));
            size_t ra = bm + r;
            *(__nv_bfloat162*)(g_hhi + ra * FFN_ + f) = __halves2bfloat162(p0, p1);
            *(__nv_bfloat162*)(g_hlo + ra * FFN_ + f) = __halves2bfloat162(l0, l1);
        }
    }
}

// ---------------- mean pool + classifier -------------------------------------
__global__ void k_pool() {
    int b = blockIdx.x;
    int c = blockIdx.y;
    int e = threadIdx.x;
    int base = b * S_ + c * 128;
    float s = 0.f;
#pragma unroll 4
    for (int i = 0; i < 128; i++) s += g_x[(size_t)(base + i) * E_ + e];
    g_pp[(b * 16 + c) * E_ + e] = s;
}

__global__ void k_cls(const float* __restrict__ w, const float* __restrict__ cb,
                      float* __restrict__ out) {
    int t = threadIdx.x;
    if (t < B_ * C_) {
        int b = t / C_, c = t % C_;
        float s = cb[c];
        for (int e = 0; e < E_; e++) {
            float p = 0.f;
#pragma unroll
            for (int j = 0; j < 16; j++) p += g_pp[(b * 16 + j) * E_ + e];
            s += (p * (1.0f / (float)S_)) * w[e * C_ + c];
        }
        out[b * C_ + c] = s;
    }
}

// ---------------- host launcher ----------------------------------------------
extern "C" void kernel_launch(void* const* d_in, const int* in_sizes, int n_in,
                              void* d_out, int out_size) {
    const int*   tokens     = (const int*)d_in[0];
    const float* embed      = (const float*)d_in[1];
    const float* attn_theta = (const float*)d_in[2];
    const float* combine_w  = (const float*)d_in[3];
    const float* combine_b  = (const float*)d_in[4];
    const float* ffn_theta  = (const float*)d_in[5];
    const float* lin1_w     = (const float*)d_in[6];
    const float* lin1_b     = (const float*)d_in[7];
    const float* lin2_w     = (const float*)d_in[8];
    const float* lin2_b     = (const float*)d_in[9];
    const float* ln1_g      = (const float*)d_in[10];
    const float* ln1_b      = (const float*)d_in[11];
    const float* ln2_g      = (const float*)d_in[12];
    const float* ln2_b      = (const float*)d_in[13];
    const float* cls_w      = (const float*)d_in[14];
    const float* cls_b      = (const float*)d_in[15];
    float* out = (float*)d_out;

    __nv_bfloat16 *ahi, *alo, *hhi, *hlo, *whi, *wlo;
    cudaGetSymbolAddress((void**)&ahi, g_ahi);
    cudaGetSymbolAddress((void**)&alo, g_alo);
    cudaGetSymbolAddress((void**)&hhi, g_hhi);
    cudaGetSymbolAddress((void**)&hlo, g_hlo);
    cudaGetSymbolAddress((void**)&whi, g_whi);
    cudaGetSymbolAddress((void**)&wlo, g_wlo);

    const int SMEM = 3 * STG;   // 76800
    cudaFuncSetAttribute(k_gf<256, 0>, cudaFuncAttributeMaxDynamicSharedMemorySize, SMEM);
    cudaFuncSetAttribute(k_gf<512, 1>, cudaFuncAttributeMaxDynamicSharedMemorySize, SMEM);
    cudaFuncSetAttribute(k_gf<512, 2>, cudaFuncAttributeMaxDynamicSharedMemorySize, SMEM);

    k_embed<<<M_, 256>>>(tokens, embed, attn_theta);   // layer-0 prep fused
    k_convw<<<dim3(256, 4), 256>>>(combine_w, lin2_w);

    // layer 0
    k_gf<256, 0><<<M_ / 64, 256, SMEM>>>(
        ahi, alo, whi + 0 * 131072, wlo + 0 * 131072, combine_b + 0 * E_,
        ln1_g + 0 * E_, ln1_b + 0 * E_, nullptr,
        ffn_theta + 0 * NQ_, lin1_w + 0 * NQ_ * FFN_, lin1_b + 0 * FFN_);
    k_gf<512, 1><<<M_ / 64, 256, SMEM>>>(
        hhi, hlo, whi + 2 * 131072, wlo + 2 * 131072, lin2_b + 0 * E_,
        ln2_g + 0 * E_, ln2_b + 0 * E_, attn_theta + 1 * 64,
        nullptr, nullptr, nullptr);
    // layer 1
    k_gf<256, 0><<<M_ / 64, 256, SMEM>>>(
        ahi, alo, whi + 1 * 131072, wlo + 1 * 131072, combine_b + 1 * E_,
        ln1_g + 1 * E_, ln1_b + 1 * E_, nullptr,
        ffn_theta + 1 * NQ_, lin1_w + 1 * NQ_ * FFN_, lin1_b + 1 * FFN_);
    k_gf<512, 2><<<M_ / 64, 256, SMEM>>>(
        hhi, hlo, whi + 3 * 131072, wlo + 3 * 131072, lin2_b + 1 * E_,
        ln2_g + 1 * E_, ln2_b + 1 * E_, nullptr,
        nullptr, nullptr, nullptr);

    k_pool<<<dim3(B_, 16), 256>>>();
    k_cls<<<1, 32>>>(cls_w, cls_b, out);
}

// round 5
// speedup vs baseline: 2.1043x; 1.1595x over previous
#include <cuda_runtime.h>
#include <cuda_bf16.h>
#include <cstdint>
#include <math.h>

#define B_   16
#define S_   2048
#define E_   256
#define L_   2
#define NQ_  8
#define FFN_ 512
#define C_   2
#define M_   (B_*S_)   // 32768 rows

// ---------------- scratch (__device__ globals; no allocations) ---------------
__device__ float g_x[(size_t)M_*E_];                             // 32 MB
__device__ float g_q[(size_t)M_*NQ_];                            // 1 MB ffn1 input
__device__ __align__(128) __nv_bfloat16 g_ahi[(size_t)M_*E_];    // 16 MB attn A hi
__device__ __align__(128) __nv_bfloat16 g_alo[(size_t)M_*E_];    // 16 MB attn A lo
__device__ __align__(128) __nv_bfloat16 g_whi[4*256*512];        // Wt[n][k] hi
__device__ __align__(128) __nv_bfloat16 g_wlo[4*256*512];        // Wt[n][k] lo
__device__ float g_pp[256*E_];                                   // pool partials

// ---------------- PTX helpers (plain sm_80+ features) ------------------------
__device__ __forceinline__ uint32_t s2u(const void* p) {
    uint32_t a;
    asm("{ .reg .u64 t; cvta.to.shared.u64 t, %1; cvt.u32.u64 %0, t; }"
        : "=r"(a) : "l"(p));
    return a;
}
__device__ __forceinline__ void cp16(uint32_t dst, const void* src) {
    asm volatile("cp.async.cg.shared.global [%0], [%1], 16;" :: "r"(dst), "l"(src));
}
__device__ __forceinline__ void cp_commit() {
    asm volatile("cp.async.commit_group;" ::: "memory");
}
__device__ __forceinline__ void cp_wait1() {
    asm volatile("cp.async.wait_group 1;" ::: "memory");
}
__device__ __forceinline__ void cp_wait0() {
    asm volatile("cp.async.wait_group 0;" ::: "memory");
}
__device__ __forceinline__ void ldm_x4(uint32_t& r0, uint32_t& r1, uint32_t& r2,
                                       uint32_t& r3, uint32_t addr) {
    asm volatile("ldmatrix.sync.aligned.m8n8.x4.shared.b16 {%0,%1,%2,%3}, [%4];"
                 : "=r"(r0), "=r"(r1), "=r"(r2), "=r"(r3) : "r"(addr));
}
__device__ __forceinline__ void ldm_x2(uint32_t& r0, uint32_t& r1, uint32_t addr) {
    asm volatile("ldmatrix.sync.aligned.m8n8.x2.shared.b16 {%0,%1}, [%2];"
                 : "=r"(r0), "=r"(r1) : "r"(addr));
}
__device__ __forceinline__ void mma16816(float* c, uint32_t a0, uint32_t a1,
                                         uint32_t a2, uint32_t a3,
                                         uint32_t b0, uint32_t b1) {
    asm volatile(
        "mma.sync.aligned.m16n8k16.row.col.f32.bf16.bf16.f32 "
        "{%0,%1,%2,%3}, {%4,%5,%6,%7}, {%8,%9}, {%0,%1,%2,%3};"
        : "+f"(c[0]), "+f"(c[1]), "+f"(c[2]), "+f"(c[3])
        : "r"(a0), "r"(a1), "r"(a2), "r"(a3), "r"(b0), "r"(b1));
}

// ---------------- embed + PE + fused prep for layer-0 attn -------------------
__global__ void k_embed(const int* __restrict__ tok, const float* __restrict__ emb,
                        const float* __restrict__ th) {
    int row = blockIdx.x;
    int e   = threadIdx.x;
    int t   = tok[row];
    int s   = row & (S_ - 1);
    int i   = e >> 1;
    float freq = expf(-(float)(2 * i) * (9.210340371976184f / (float)E_));
    float ang  = (float)s * freq;
    float pe   = (e & 1) ? cosf(ang) : sinf(ang);
    size_t idx = (size_t)row * E_ + e;
    float x = emb[(size_t)t * E_ + e] + pe;
    g_x[idx] = x;
    float a = cosf(x + th[e & 63]);
    __nv_bfloat16 hi = __float2bfloat16(a);
    g_ahi[idx] = hi;
    g_alo[idx] = __float2bfloat16(a - __bfloat162float(hi));
}

// ---------------- weight convert + transpose ---------------------------------
__global__ void k_convw(const float* __restrict__ cw, const float* __restrict__ l2w) {
    int slot = blockIdx.y;               // 0,1: combine (K=256); 2,3: lin2 (K=512)
    int n    = blockIdx.x;
    int K    = (slot < 2) ? 256 : 512;
    const float* src = (slot < 2) ? (cw + (size_t)slot * E_ * E_)
                                  : (l2w + (size_t)(slot - 2) * FFN_ * E_);
    for (int k = threadIdx.x; k < K; k += 256) {
        float w = src[(size_t)k * E_ + n];
        __nv_bfloat16 hi = __float2bfloat16(w);
        float lo = w - __bfloat162float(hi);
        size_t o = (size_t)slot * 131072 + (size_t)n * K + k;
        g_whi[o] = hi;
        g_wlo[o] = __float2bfloat16(lo);
    }
}

// ---------------- fused GEMM (interleaved 3-term) + LN + producers -----------
// BM=128, BN=256, BK=32, 512 threads (4M x 4N warps, warp tile 32x64).
// Per k-chunk: load {Ahi,Alo,Whi,Wlo} once; issue hi*hi + lo*hi + hi*lo.
// MODE 0: attn GEMM -> LN1 -> write g_x + q=cos(x[:,:8])cos(fth) (g_q)
// MODE 1: ffn GEMM  -> LN2 -> write g_x + cos(x+thetaNext) hi/lo
// MODE 2: ffn GEMM  -> LN2 -> pool partials only (no g_x store)
// COMPA:  A-tiles computed in-kernel from q/W1/b1 (ffn2); else cp.async.
#define ROWB    80
#define A_LO_O  10240
#define W_HI_O  20480
#define W_LO_O  40960
#define STAGE   61440
#define Q_OFF   (3*STAGE)            // 184320, 4096 B
#define W1_OFF  (Q_OFF + 4096)       // 18432 B (512 x 9 floats, padded)
#define B1_OFF  (W1_OFF + 18432)     // 2048 B
#define SME_ATT (3*STAGE)            // 184320
#define SME_FFN (B1_OFF + 2048)      // 208896

template <int K, int MODE, bool COMPA>
__global__ void __launch_bounds__(512, 1)
k_gf(const __nv_bfloat16* __restrict__ Agh, const __nv_bfloat16* __restrict__ Agl,
     const __nv_bfloat16* __restrict__ Whi, const __nv_bfloat16* __restrict__ Wlo,
     const float* __restrict__ bias,
     const float* __restrict__ lnG, const float* __restrict__ lnB,
     const float* __restrict__ thN,                       // MODE 1
     const float* __restrict__ fTh,                       // MODE 0
     const float* __restrict__ qg, const float* __restrict__ W1,
     const float* __restrict__ b1) {                      // COMPA
    constexpr int CH = K >> 5;
    extern __shared__ __align__(16) char smem[];
    uint32_t sb = s2u(smem);
    int tid = threadIdx.x, lane = tid & 31, wid = tid >> 5;
    int wm = wid >> 2, wn = wid & 3;
    size_t bm = (size_t)blockIdx.x * 128;

    float* qsh = (float*)(smem + Q_OFF);
    float* w1t = (float*)(smem + W1_OFF);
    float* b1s = (float*)(smem + B1_OFF);

    if constexpr (COMPA) {
        for (int i = tid; i < 1024; i += 512) qsh[i] = qg[bm * 8 + i];
        for (int i = tid; i < 4096; i += 512) {
            int f = i >> 3, n = i & 7;
            w1t[f * 9 + n] = W1[n * FFN_ + f];
        }
        if (tid < 512) b1s[tid] = b1[tid];
        __syncthreads();
    }

    float acc[2][8][4];
#pragma unroll
    for (int i = 0; i < 2; i++)
#pragma unroll
        for (int j = 0; j < 8; j++)
#pragma unroll
            for (int c = 0; c < 4; c++) acc[i][j][c] = 0.f;

    int part = tid & 3, rb = tid >> 2;

    auto load_stage = [&](int st, int ch) {
        uint32_t dst = sb + st * STAGE;
        int kk = ch << 5;
        if constexpr (!COMPA) {
            cp16(dst + (uint32_t)rb * ROWB + part * 16,
                 Agh + (bm + rb) * (size_t)K + kk + part * 8);
            cp16(dst + A_LO_O + (uint32_t)rb * ROWB + part * 16,
                 Agl + (bm + rb) * (size_t)K + kk + part * 8);
        }
        cp16(dst + W_HI_O + (uint32_t)rb * ROWB + part * 16,
             Whi + (size_t)rb * K + kk + part * 8);
        cp16(dst + W_HI_O + (uint32_t)(rb + 128) * ROWB + part * 16,
             Whi + (size_t)(rb + 128) * K + kk + part * 8);
        cp16(dst + W_LO_O + (uint32_t)rb * ROWB + part * 16,
             Wlo + (size_t)rb * K + kk + part * 8);
        cp16(dst + W_LO_O + (uint32_t)(rb + 128) * ROWB + part * 16,
             Wlo + (size_t)(rb + 128) * K + kk + part * 8);
        cp_commit();
    };

    auto comp_a = [&](int st, int ch) {
        char* dst = smem + st * STAGE;
        int r = tid >> 2, c0 = (tid & 3) * 8, f0 = ch << 5;
        float qr[8];
#pragma unroll
        for (int n = 0; n < 8; n++) qr[n] = qsh[r * 8 + n];
        __nv_bfloat162 hp[4], lp[4];
#pragma unroll
        for (int jj = 0; jj < 4; jj++) {
            float hv[2];
#pragma unroll
            for (int u = 0; u < 2; u++) {
                int f = f0 + c0 + jj * 2 + u;
                float h = b1s[f];
#pragma unroll
                for (int n = 0; n < 8; n++) h += qr[n] * w1t[f * 9 + n];
                hv[u] = fmaxf(h, 0.f);
            }
            __nv_bfloat16 p0 = __float2bfloat16(hv[0]);
            __nv_bfloat16 p1 = __float2bfloat16(hv[1]);
            hp[jj] = __halves2bfloat162(p0, p1);
            lp[jj] = __halves2bfloat162(__float2bfloat16(hv[0] - __bfloat162float(p0)),
                                        __float2bfloat16(hv[1] - __bfloat162float(p1)));
        }
        *(uint4*)(dst + r * ROWB + c0 * 2) = *(uint4*)hp;
        *(uint4*)(dst + A_LO_O + r * ROWB + c0 * 2) = *(uint4*)lp;
    };

    load_stage(0, 0);
    load_stage(1, 1);
    if constexpr (COMPA) { comp_a(0, 0); comp_a(1, 1); }

    for (int cc = 0; cc < CH; cc++) {
        if (cc + 1 < CH) cp_wait1(); else cp_wait0();
        __syncthreads();
        if (cc + 2 < CH) {
            load_stage((cc + 2) % 3, cc + 2);
            if constexpr (COMPA) comp_a((cc + 2) % 3, cc + 2);
        }

        uint32_t stg = sb + (cc % 3) * STAGE;
        uint32_t aHi = stg + (wm * 32 + (lane & 15)) * ROWB + (lane >> 4) * 16;
        uint32_t bHi = stg + W_HI_O + (wn * 64 + (lane & 7)) * ROWB + ((lane >> 3) & 1) * 16;

#pragma unroll
        for (int kb = 0; kb < 2; kb++) {
            uint32_t ko = kb * 32;
            uint32_t b0[8], b1r[8];
#pragma unroll
            for (int ni = 0; ni < 8; ni++)
                ldm_x2(b0[ni], b1r[ni], bHi + ni * 8 * ROWB + ko);
            uint32_t h0[2], h1[2], h2[2], h3[2];
#pragma unroll
            for (int mi = 0; mi < 2; mi++)
                ldm_x4(h0[mi], h1[mi], h2[mi], h3[mi], aHi + mi * 16 * ROWB + ko);
#pragma unroll
            for (int mi = 0; mi < 2; mi++)
#pragma unroll
                for (int ni = 0; ni < 8; ni++)
                    mma16816(acc[mi][ni], h0[mi], h1[mi], h2[mi], h3[mi], b0[ni], b1r[ni]);
            uint32_t l0[2], l1[2], l2[2], l3[2];
#pragma unroll
            for (int mi = 0; mi < 2; mi++)
                ldm_x4(l0[mi], l1[mi], l2[mi], l3[mi], aHi + A_LO_O + mi * 16 * ROWB + ko);
#pragma unroll
            for (int mi = 0; mi < 2; mi++)
#pragma unroll
                for (int ni = 0; ni < 8; ni++)
                    mma16816(acc[mi][ni], l0[mi], l1[mi], l2[mi], l3[mi], b0[ni], b1r[ni]);
#pragma unroll
            for (int ni = 0; ni < 8; ni++)
                ldm_x2(b0[ni], b1r[ni], bHi + 20480 + ni * 8 * ROWB + ko);
#pragma unroll
            for (int mi = 0; mi < 2; mi++)
#pragma unroll
                for (int ni = 0; ni < 8; ni++)
                    mma16816(acc[mi][ni], h0[mi], h1[mi], h2[mi], h3[mi], b0[ni], b1r[ni]);
        }
    }
    __syncthreads();

    // ---------- epilogue: residual + LayerNorm (+ producers) ----------
    float2* red = (float2*)smem;                  // [128][4]
    float2* mr  = (float2*)(smem + 4096);         // [128]
    float*  pps = (float*)(smem + 8192);          // [4][256] (MODE 2)

    int mcol = wn * 64 + (lane & 3) * 2;
    int r0l  = wm * 32 + (lane >> 2);

#pragma unroll
    for (int mi = 0; mi < 2; mi++) {
        float s0 = 0, q0 = 0, s1 = 0, q1 = 0;
        size_t ra = bm + r0l + mi * 16;
#pragma unroll
        for (int ni = 0; ni < 8; ni++) {
            int col = mcol + ni * 8;
            float2 x0 = *(const float2*)(g_x + ra * E_ + col);
            float2 x1 = *(const float2*)(g_x + (ra + 8) * E_ + col);
            float bcx = bias[col], bcy = bias[col + 1];
            float v0 = acc[mi][ni][0] + bcx + x0.x;
            float v1 = acc[mi][ni][1] + bcy + x0.y;
            float v2 = acc[mi][ni][2] + bcx + x1.x;
            float v3 = acc[mi][ni][3] + bcy + x1.y;
            acc[mi][ni][0] = v0; acc[mi][ni][1] = v1;
            acc[mi][ni][2] = v2; acc[mi][ni][3] = v3;
            s0 += v0 + v1; q0 += v0 * v0 + v1 * v1;
            s1 += v2 + v3; q1 += v2 * v2 + v3 * v3;
        }
#pragma unroll
        for (int o = 1; o <= 2; o <<= 1) {
            s0 += __shfl_xor_sync(0xffffffffu, s0, o);
            q0 += __shfl_xor_sync(0xffffffffu, q0, o);
            s1 += __shfl_xor_sync(0xffffffffu, s1, o);
            q1 += __shfl_xor_sync(0xffffffffu, q1, o);
        }
        if ((lane & 3) == 0) {
            int rl = r0l + mi * 16;
            red[rl * 4 + wn] = make_float2(s0, q0);
            red[(rl + 8) * 4 + wn] = make_float2(s1, q1);
        }
    }
    __syncthreads();
    if (tid < 128) {
        float s = 0, q = 0;
#pragma unroll
        for (int j = 0; j < 4; j++) { float2 t = red[tid * 4 + j]; s += t.x; q += t.y; }
        float mean = s * (1.0f / E_);
        float var  = q * (1.0f / E_) - mean * mean;
        mr[tid] = make_float2(mean, rsqrtf(var + 1e-5f));
    }
    __syncthreads();

    float cf0 = 0.f, cf1 = 0.f;
    if constexpr (MODE == 0) {
        int c = (lane & 3) * 2;
        cf0 = cosf(fTh[c]); cf1 = cosf(fTh[c + 1]);
    }
    float ps[8][2];
    if constexpr (MODE == 2) {
#pragma unroll
        for (int ni = 0; ni < 8; ni++) { ps[ni][0] = 0.f; ps[ni][1] = 0.f; }
    }

#pragma unroll
    for (int mi = 0; mi < 2; mi++) {
        int rl = r0l + mi * 16;
        float2 m0 = mr[rl], m1 = mr[rl + 8];
        size_t ra = bm + rl;
#pragma unroll
        for (int ni = 0; ni < 8; ni++) {
            int col = mcol + ni * 8;
            float gx = lnG[col], gy = lnG[col + 1];
            float bx = lnB[col], by = lnB[col + 1];
            float o0 = (acc[mi][ni][0] - m0.x) * m0.y * gx + bx;
            float o1 = (acc[mi][ni][1] - m0.x) * m0.y * gy + by;
            float o2 = (acc[mi][ni][2] - m1.x) * m1.y * gx + bx;
            float o3 = (acc[mi][ni][3] - m1.x) * m1.y * gy + by;
            if constexpr (MODE != 2) {
                *(float2*)(g_x + ra * E_ + col) = make_float2(o0, o1);
                *(float2*)(g_x + (ra + 8) * E_ + col) = make_float2(o2, o3);
            }
            if constexpr (MODE == 0) {
                if (wn == 0 && ni == 0) {
                    int c = (lane & 3) * 2;
                    g_q[ra * 8 + c]           = cosf(o0) * cf0;
                    g_q[ra * 8 + c + 1]       = cosf(o1) * cf1;
                    g_q[(ra + 8) * 8 + c]     = cosf(o2) * cf0;
                    g_q[(ra + 8) * 8 + c + 1] = cosf(o3) * cf1;
                }
            }
            if constexpr (MODE == 1) {
                float t0 = thN[col & 63], t1 = thN[(col + 1) & 63];
                float a0 = cosf(o0 + t0), a1 = cosf(o1 + t1);
                float a2 = cosf(o2 + t0), a3 = cosf(o3 + t1);
                __nv_bfloat16 p0 = __float2bfloat16(a0), p1 = __float2bfloat16(a1);
                __nv_bfloat16 p2 = __float2bfloat16(a2), p3 = __float2bfloat16(a3);
                *(__nv_bfloat162*)(g_ahi + ra * E_ + col) = __halves2bfloat162(p0, p1);
                *(__nv_bfloat162*)(g_ahi + (ra + 8) * E_ + col) = __halves2bfloat162(p2, p3);
                *(__nv_bfloat162*)(g_alo + ra * E_ + col) =
                    __halves2bfloat162(__float2bfloat16(a0 - __bfloat162float(p0)),
                                       __float2bfloat16(a1 - __bfloat162float(p1)));
                *(__nv_bfloat162*)(g_alo + (ra + 8) * E_ + col) =
                    __halves2bfloat162(__float2bfloat16(a2 - __bfloat162float(p2)),
                                       __float2bfloat16(a3 - __bfloat162float(p3)));
            }
            if constexpr (MODE == 2) {
                ps[ni][0] += o0 + o2;
                ps[ni][1] += o1 + o3;
            }
        }
    }

    if constexpr (MODE == 2) {
#pragma unroll
        for (int ni = 0; ni < 8; ni++)
#pragma unroll
            for (int o = 4; o <= 16; o <<= 1) {
                ps[ni][0] += __shfl_xor_sync(0xffffffffu, ps[ni][0], o);
                ps[ni][1] += __shfl_xor_sync(0xffffffffu, ps[ni][1], o);
            }
        if (lane < 4) {
#pragma unroll
            for (int ni = 0; ni < 8; ni++) {
                pps[wm * 256 + mcol + ni * 8]     = ps[ni][0];
                pps[wm * 256 + mcol + ni * 8 + 1] = ps[ni][1];
            }
        }
        __syncthreads();
        if (tid < 256) {
            float s = pps[tid] + pps[256 + tid] + pps[512 + tid] + pps[768 + tid];
            g_pp[blockIdx.x * 256 + tid] = s;
        }
    }
}

// ---------------- classifier (sums 16 pool partials per batch) ---------------
__global__ void k_cls(const float* __restrict__ w, const float* __restrict__ cb,
                      float* __restrict__ out) {
    int t = threadIdx.x;
    if (t < B_ * C_) {
        int b = t / C_, c = t % C_;
        float s = cb[c];
        for (int e = 0; e < E_; e++) {
            float p = 0.f;
#pragma unroll
            for (int j = 0; j < 16; j++) p += g_pp[(b * 16 + j) * E_ + e];
            s += (p * (1.0f / (float)S_)) * w[e * C_ + c];
        }
        out[b * C_ + c] = s;
    }
}

// ---------------- host launcher ----------------------------------------------
extern "C" void kernel_launch(void* const* d_in, const int* in_sizes, int n_in,
                              void* d_out, int out_size) {
    const int*   tokens     = (const int*)d_in[0];
    const float* embed      = (const float*)d_in[1];
    const float* attn_theta = (const float*)d_in[2];
    const float* combine_w  = (const float*)d_in[3];
    const float* combine_b  = (const float*)d_in[4];
    const float* ffn_theta  = (const float*)d_in[5];
    const float* lin1_w     = (const float*)d_in[6];
    const float* lin1_b     = (const float*)d_in[7];
    const float* lin2_w     = (const float*)d_in[8];
    const float* lin2_b     = (const float*)d_in[9];
    const float* ln1_g      = (const float*)d_in[10];
    const float* ln1_b      = (const float*)d_in[11];
    const float* ln2_g      = (const float*)d_in[12];
    const float* ln2_b      = (const float*)d_in[13];
    const float* cls_w      = (const float*)d_in[14];
    const float* cls_b      = (const float*)d_in[15];
    float* out = (float*)d_out;

    __nv_bfloat16 *ahi, *alo, *whi, *wlo;
    float *qp;
    cudaGetSymbolAddress((void**)&ahi, g_ahi);
    cudaGetSymbolAddress((void**)&alo, g_alo);
    cudaGetSymbolAddress((void**)&whi, g_whi);
    cudaGetSymbolAddress((void**)&wlo, g_wlo);
    cudaGetSymbolAddress((void**)&qp,  g_q);

    cudaFuncSetAttribute(k_gf<256, 0, false>, cudaFuncAttributeMaxDynamicSharedMemorySize, SME_ATT);
    cudaFuncSetAttribute(k_gf<512, 1, true>,  cudaFuncAttributeMaxDynamicSharedMemorySize, SME_FFN);
    cudaFuncSetAttribute(k_gf<512, 2, true>,  cudaFuncAttributeMaxDynamicSharedMemorySize, SME_FFN);

    k_embed<<<M_, 256>>>(tokens, embed, attn_theta);
    k_convw<<<dim3(256, 4), 256>>>(combine_w, lin2_w);

    // layer 0
    k_gf<256, 0, false><<<M_ / 128, 512, SME_ATT>>>(
        ahi, alo, whi + 0 * 131072, wlo + 0 * 131072, combine_b + 0 * E_,
        ln1_g + 0 * E_, ln1_b + 0 * E_, nullptr,
        ffn_theta + 0 * NQ_, nullptr, nullptr, nullptr);
    k_gf<512, 1, true><<<M_ / 128, 512, SME_FFN>>>(
        nullptr, nullptr, whi + 2 * 131072, wlo + 2 * 131072, lin2_b + 0 * E_,
        ln2_g + 0 * E_, ln2_b + 0 * E_, attn_theta + 1 * 64,
        nullptr, qp, lin1_w + 0 * NQ_ * FFN_, lin1_b + 0 * FFN_);
    // layer 1
    k_gf<256, 0, false><<<M_ / 128, 512, SME_ATT>>>(
        ahi, alo, whi + 1 * 131072, wlo + 1 * 131072, combine_b + 1 * E_,
        ln1_g + 1 * E_, ln1_b + 1 * E_, nullptr,
        ffn_theta + 1 * NQ_, nullptr, nullptr, nullptr);
    k_gf<512, 2, true><<<M_ / 128, 512, SME_FFN>>>(
        nullptr, nullptr, whi + 3 * 131072, wlo + 3 * 131072, lin2_b + 1 * E_,
        ln2_g + 1 * E_, ln2_b + 1 * E_, nullptr,
        nullptr, qp, lin1_w + 1 * NQ_ * FFN_, lin1_b + 1 * FFN_);

    k_cls<<<1, 32>>>(cls_w, cls_b, out);
}

// round 6
// speedup vs baseline: 2.6673x; 1.2676x over previous
#include <cuda_runtime.h>
#include <cuda_bf16.h>
#include <cstdint>
#include <math.h>

#define B_   16
#define S_   2048
#define E_   256
#define L_   2
#define NQ_  8
#define FFN_ 512
#define C_   2
#define M_   (B_*S_)   // 32768 rows

// ---------------- scratch (__device__ globals; no allocations) ---------------
__device__ float g_x[(size_t)M_*E_];                             // 32 MB
__device__ float g_q[(size_t)M_*NQ_];                            // 1 MB
__device__ __align__(128) __nv_bfloat16 g_ahi[(size_t)M_*E_];    // 16 MB
__device__ __align__(128) __nv_bfloat16 g_alo[(size_t)M_*E_];    // 16 MB
__device__ __align__(128) __nv_bfloat16 g_whi[4*256*512];        // Wt[n][k] hi
__device__ __align__(128) __nv_bfloat16 g_wlo[4*256*512];        // Wt[n][k] lo
__device__ float g_pp[512*E_];                                   // pool partials

// ---------------- PTX helpers ------------------------------------------------
__device__ __forceinline__ uint32_t s2u(const void* p) {
    uint32_t a;
    asm("{ .reg .u64 t; cvta.to.shared.u64 t, %1; cvt.u32.u64 %0, t; }"
        : "=r"(a) : "l"(p));
    return a;
}
__device__ __forceinline__ void cp16(uint32_t dst, const void* src) {
    asm volatile("cp.async.cg.shared.global [%0], [%1], 16;" :: "r"(dst), "l"(src));
}
__device__ __forceinline__ void cp_commit() {
    asm volatile("cp.async.commit_group;" ::: "memory");
}
__device__ __forceinline__ void cp_wait0() {
    asm volatile("cp.async.wait_group 0;" ::: "memory");
}
__device__ __forceinline__ void ldm_x4(uint32_t& r0, uint32_t& r1, uint32_t& r2,
                                       uint32_t& r3, uint32_t addr) {
    asm volatile("ldmatrix.sync.aligned.m8n8.x4.shared.b16 {%0,%1,%2,%3}, [%4];"
                 : "=r"(r0), "=r"(r1), "=r"(r2), "=r"(r3) : "r"(addr));
}
__device__ __forceinline__ void ldm_x2(uint32_t& r0, uint32_t& r1, uint32_t addr) {
    asm volatile("ldmatrix.sync.aligned.m8n8.x2.shared.b16 {%0,%1}, [%2];"
                 : "=r"(r0), "=r"(r1) : "r"(addr));
}
__device__ __forceinline__ void mma16816(float* c, uint32_t a0, uint32_t a1,
                                         uint32_t a2, uint32_t a3,
                                         uint32_t b0, uint32_t b1) {
    asm volatile(
        "mma.sync.aligned.m16n8k16.row.col.f32.bf16.bf16.f32 "
        "{%0,%1,%2,%3}, {%4,%5,%6,%7}, {%8,%9}, {%0,%1,%2,%3};"
        : "+f"(c[0]), "+f"(c[1]), "+f"(c[2]), "+f"(c[3])
        : "r"(a0), "r"(a1), "r"(a2), "r"(a3), "r"(b0), "r"(b1));
}

// ---------------- embed + PE + fused prep for layer-0 attn -------------------
__global__ void k_embed(const int* __restrict__ tok, const float* __restrict__ emb,
                        const float* __restrict__ th) {
    int row = blockIdx.x;
    int e   = threadIdx.x;
    int t   = tok[row];
    int s   = row & (S_ - 1);
    int i   = e >> 1;
    float freq = expf(-(float)(2 * i) * (9.210340371976184f / (float)E_));
    float ang  = (float)s * freq;
    float pe   = (e & 1) ? cosf(ang) : sinf(ang);
    size_t idx = (size_t)row * E_ + e;
    float x = emb[(size_t)t * E_ + e] + pe;
    g_x[idx] = x;
    float a = cosf(x + th[e & 63]);
    __nv_bfloat16 hi = __float2bfloat16(a);
    g_ahi[idx] = hi;
    g_alo[idx] = __float2bfloat16(a - __bfloat162float(hi));
}

// ---------------- weight convert + transpose ---------------------------------
__global__ void k_convw(const float* __restrict__ cw, const float* __restrict__ l2w) {
    int slot = blockIdx.y;
    int n    = blockIdx.x;
    int K    = (slot < 2) ? 256 : 512;
    const float* src = (slot < 2) ? (cw + (size_t)slot * E_ * E_)
                                  : (l2w + (size_t)(slot - 2) * FFN_ * E_);
    for (int k = threadIdx.x; k < K; k += 256) {
        float w = src[(size_t)k * E_ + n];
        __nv_bfloat16 hi = __float2bfloat16(w);
        float lo = w - __bfloat162float(hi);
        size_t o = (size_t)slot * 131072 + (size_t)n * K + k;
        g_whi[o] = hi;
        g_wlo[o] = __float2bfloat16(lo);
    }
}

// ---------------- fused GEMM (interleaved 3-term) + LN + producers -----------
// BM=64, BN=256, BK=32, 256 threads (2M x 4N warps, warp tile 32x64).
// 64B smem rows with XOR swizzle (chunk ^= (row>>1)&3), 2-stage pipeline,
// 2 CTAs/SM for mainloop/epilogue overlap.
#define A_HI_O  0
#define A_LO_O  4096
#define W_HI_O  8192
#define W_LO_O  24576
#define STAGE   40960
#define Q_OFF   (2*STAGE)            // 81920, 2048 B
#define W1_OFF  (Q_OFF + 2048)       // 18432 B (512 x 9 floats)
#define B1_OFF  (W1_OFF + 18432)     // 2048 B
#define SME_ATT (2*STAGE)            // 81920
#define SME_FFN (B1_OFF + 2048)      // 104448

template <int K, int MODE, bool COMPA>
__global__ void __launch_bounds__(256, 2)
k_gf(const __nv_bfloat16* __restrict__ Agh, const __nv_bfloat16* __restrict__ Agl,
     const __nv_bfloat16* __restrict__ Whi, const __nv_bfloat16* __restrict__ Wlo,
     const float* __restrict__ bias,
     const float* __restrict__ lnG, const float* __restrict__ lnB,
     const float* __restrict__ thN,                       // MODE 1
     const float* __restrict__ fTh,                       // MODE 0
     const float* __restrict__ qg, const float* __restrict__ W1,
     const float* __restrict__ b1) {                      // COMPA
    constexpr int CH = K >> 5;
    extern __shared__ __align__(16) char smem[];
    uint32_t sb = s2u(smem);
    int tid = threadIdx.x, lane = tid & 31, wid = tid >> 5;
    int wm = wid >> 2, wn = wid & 3;
    size_t bm = (size_t)blockIdx.x * 64;

    float* qsh = (float*)(smem + Q_OFF);
    float* w1t = (float*)(smem + W1_OFF);
    float* b1s = (float*)(smem + B1_OFF);

    if constexpr (COMPA) {
        for (int i = tid; i < 512; i += 256) qsh[i] = qg[bm * 8 + i];
        for (int i = tid; i < 4096; i += 256) {
            int f = i >> 3, n = i & 7;
            w1t[f * 9 + n] = W1[n * FFN_ + f];
        }
        for (int i = tid; i < 512; i += 256) b1s[i] = b1[i];
        __syncthreads();
    }

    float acc[2][8][4];
#pragma unroll
    for (int i = 0; i < 2; i++)
#pragma unroll
        for (int j = 0; j < 8; j++)
#pragma unroll
            for (int c = 0; c < 4; c++) acc[i][j][c] = 0.f;

    int part = tid & 3, rb = tid >> 2;               // rb 0..63
    uint32_t swc = (uint32_t)(part ^ ((rb >> 1) & 3)) << 4;

    auto load_stage = [&](int st, int ch) {
        uint32_t dst = sb + st * STAGE;
        int kk = ch << 5;
        if constexpr (!COMPA) {
            cp16(dst + A_HI_O + rb * 64 + swc,
                 Agh + (bm + rb) * (size_t)K + kk + part * 8);
            cp16(dst + A_LO_O + rb * 64 + swc,
                 Agl + (bm + rb) * (size_t)K + kk + part * 8);
        }
#pragma unroll
        for (int i = 0; i < 4; i++) {
            int r = rb + i * 64;
            cp16(dst + W_HI_O + r * 64 + swc, Whi + (size_t)r * K + kk + part * 8);
            cp16(dst + W_LO_O + r * 64 + swc, Wlo + (size_t)r * K + kk + part * 8);
        }
        cp_commit();
    };

    auto comp_a = [&](int st, int ch) {
        char* dst = smem + st * STAGE;
        int r = rb, f0 = (ch << 5) + part * 8;
        float qr[8];
#pragma unroll
        for (int n = 0; n < 8; n++) qr[n] = qsh[r * 8 + n];
        __nv_bfloat162 hp[4], lp[4];
#pragma unroll
        for (int jj = 0; jj < 4; jj++) {
            float hv[2];
#pragma unroll
            for (int u = 0; u < 2; u++) {
                int f = f0 + jj * 2 + u;
                float h = b1s[f];
#pragma unroll
                for (int n = 0; n < 8; n++) h += qr[n] * w1t[f * 9 + n];
                hv[u] = fmaxf(h, 0.f);
            }
            __nv_bfloat16 p0 = __float2bfloat16(hv[0]);
            __nv_bfloat16 p1 = __float2bfloat16(hv[1]);
            hp[jj] = __halves2bfloat162(p0, p1);
            lp[jj] = __halves2bfloat162(__float2bfloat16(hv[0] - __bfloat162float(p0)),
                                        __float2bfloat16(hv[1] - __bfloat162float(p1)));
        }
        *(uint4*)(dst + A_HI_O + r * 64 + swc) = *(uint4*)hp;
        *(uint4*)(dst + A_LO_O + r * 64 + swc) = *(uint4*)lp;
    };

    load_stage(0, 0);
    if constexpr (COMPA) comp_a(0, 0);

    uint32_t sxA = (((uint32_t)lane & 15) >> 1) & 3;
    uint32_t sxB = (((uint32_t)lane & 7) >> 1) & 3;
    uint32_t cA  = (uint32_t)lane >> 4;
    uint32_t cB  = ((uint32_t)lane >> 3) & 1;
    uint32_t rowA = (wm * 32 + (lane & 15)) * 64;
    uint32_t rowB = (wn * 64 + (lane & 7)) * 64;

    for (int cc = 0; cc < CH; cc++) {
        cp_wait0();
        __syncthreads();
        if (cc + 1 < CH) {
            load_stage((cc + 1) & 1, cc + 1);
            if constexpr (COMPA) comp_a((cc + 1) & 1, cc + 1);
        }
        uint32_t stg = sb + (cc & 1) * STAGE;

#pragma unroll
        for (int kb = 0; kb < 2; kb++) {
            uint32_t colA = ((kb * 2 + cA) ^ sxA) << 4;
            uint32_t colB = ((kb * 2 + cB) ^ sxB) << 4;
            uint32_t b0[8], b1r[8];
#pragma unroll
            for (int ni = 0; ni < 8; ni++)
                ldm_x2(b0[ni], b1r[ni], stg + W_HI_O + rowB + ni * 512 + colB);
            uint32_t h0[2], h1[2], h2[2], h3[2];
#pragma unroll
            for (int mi = 0; mi < 2; mi++)
                ldm_x4(h0[mi], h1[mi], h2[mi], h3[mi],
                       stg + A_HI_O + rowA + mi * 1024 + colA);
#pragma unroll
            for (int mi = 0; mi < 2; mi++)
#pragma unroll
                for (int ni = 0; ni < 8; ni++)
                    mma16816(acc[mi][ni], h0[mi], h1[mi], h2[mi], h3[mi], b0[ni], b1r[ni]);
            uint32_t l0[2], l1[2], l2[2], l3[2];
#pragma unroll
            for (int mi = 0; mi < 2; mi++)
                ldm_x4(l0[mi], l1[mi], l2[mi], l3[mi],
                       stg + A_LO_O + rowA + mi * 1024 + colA);
#pragma unroll
            for (int mi = 0; mi < 2; mi++)
#pragma unroll
                for (int ni = 0; ni < 8; ni++)
                    mma16816(acc[mi][ni], l0[mi], l1[mi], l2[mi], l3[mi], b0[ni], b1r[ni]);
#pragma unroll
            for (int ni = 0; ni < 8; ni++)
                ldm_x2(b0[ni], b1r[ni], stg + W_LO_O + rowB + ni * 512 + colB);
#pragma unroll
            for (int mi = 0; mi < 2; mi++)
#pragma unroll
                for (int ni = 0; ni < 8; ni++)
                    mma16816(acc[mi][ni], h0[mi], h1[mi], h2[mi], h3[mi], b0[ni], b1r[ni]);
        }
    }
    __syncthreads();

    // ---------- epilogue: residual + LayerNorm (+ producers) ----------
    float2* red = (float2*)smem;                  // [64][4]
    float2* mr  = (float2*)(smem + 2048);         // [64]
    float*  pps = (float*)(smem + 4096);          // [2][256] (MODE 2)

    int mcol = wn * 64 + (lane & 3) * 2;
    int r0l  = wm * 32 + (lane >> 2);

#pragma unroll
    for (int mi = 0; mi < 2; mi++) {
        float s0 = 0, q0 = 0, s1 = 0, q1 = 0;
        size_t ra = bm + r0l + mi * 16;
#pragma unroll
        for (int ni = 0; ni < 8; ni++) {
            int col = mcol + ni * 8;
            float2 x0 = *(const float2*)(g_x + ra * E_ + col);
            float2 x1 = *(const float2*)(g_x + (ra + 8) * E_ + col);
            float bcx = bias[col], bcy = bias[col + 1];
            float v0 = acc[mi][ni][0] + bcx + x0.x;
            float v1 = acc[mi][ni][1] + bcy + x0.y;
            float v2 = acc[mi][ni][2] + bcx + x1.x;
            float v3 = acc[mi][ni][3] + bcy + x1.y;
            acc[mi][ni][0] = v0; acc[mi][ni][1] = v1;
            acc[mi][ni][2] = v2; acc[mi][ni][3] = v3;
            s0 += v0 + v1; q0 += v0 * v0 + v1 * v1;
            s1 += v2 + v3; q1 += v2 * v2 + v3 * v3;
        }
#pragma unroll
        for (int o = 1; o <= 2; o <<= 1) {
            s0 += __shfl_xor_sync(0xffffffffu, s0, o);
            q0 += __shfl_xor_sync(0xffffffffu, q0, o);
            s1 += __shfl_xor_sync(0xffffffffu, s1, o);
            q1 += __shfl_xor_sync(0xffffffffu, q1, o);
        }
        if ((lane & 3) == 0) {
            int rl = r0l + mi * 16;
            red[rl * 4 + wn] = make_float2(s0, q0);
            red[(rl + 8) * 4 + wn] = make_float2(s1, q1);
        }
    }
    __syncthreads();
    if (tid < 64) {
        float s = 0, q = 0;
#pragma unroll
        for (int j = 0; j < 4; j++) { float2 t = red[tid * 4 + j]; s += t.x; q += t.y; }
        float mean = s * (1.0f / E_);
        float var  = q * (1.0f / E_) - mean * mean;
        mr[tid] = make_float2(mean, rsqrtf(var + 1e-5f));
    }
    __syncthreads();

    float cf0 = 0.f, cf1 = 0.f;
    if constexpr (MODE == 0) {
        int c = (lane & 3) * 2;
        cf0 = cosf(fTh[c]); cf1 = cosf(fTh[c + 1]);
    }
    float ps[8][2];
    if constexpr (MODE == 2) {
#pragma unroll
        for (int ni = 0; ni < 8; ni++) { ps[ni][0] = 0.f; ps[ni][1] = 0.f; }
    }

#pragma unroll
    for (int mi = 0; mi < 2; mi++) {
        int rl = r0l + mi * 16;
        float2 m0 = mr[rl], m1 = mr[rl + 8];
        size_t ra = bm + rl;
#pragma unroll
        for (int ni = 0; ni < 8; ni++) {
            int col = mcol + ni * 8;
            float gx = lnG[col], gy = lnG[col + 1];
            float bx = lnB[col], by = lnB[col + 1];
            float o0 = (acc[mi][ni][0] - m0.x) * m0.y * gx + bx;
            float o1 = (acc[mi][ni][1] - m0.x) * m0.y * gy + by;
            float o2 = (acc[mi][ni][2] - m1.x) * m1.y * gx + bx;
            float o3 = (acc[mi][ni][3] - m1.x) * m1.y * gy + by;
            if constexpr (MODE != 2) {
                *(float2*)(g_x + ra * E_ + col) = make_float2(o0, o1);
                *(float2*)(g_x + (ra + 8) * E_ + col) = make_float2(o2, o3);
            }
            if constexpr (MODE == 0) {
                if (wn == 0 && ni == 0) {
                    int c = (lane & 3) * 2;
                    g_q[ra * 8 + c]           = cosf(o0) * cf0;
                    g_q[ra * 8 + c + 1]       = cosf(o1) * cf1;
                    g_q[(ra + 8) * 8 + c]     = cosf(o2) * cf0;
                    g_q[(ra + 8) * 8 + c + 1] = cosf(o3) * cf1;
                }
            }
            if constexpr (MODE == 1) {
                float t0 = thN[col & 63], t1 = thN[(col + 1) & 63];
                float a0 = cosf(o0 + t0), a1 = cosf(o1 + t1);
                float a2 = cosf(o2 + t0), a3 = cosf(o3 + t1);
                __nv_bfloat16 p0 = __float2bfloat16(a0), p1 = __float2bfloat16(a1);
                __nv_bfloat16 p2 = __float2bfloat16(a2), p3 = __float2bfloat16(a3);
                *(__nv_bfloat162*)(g_ahi + ra * E_ + col) = __halves2bfloat162(p0, p1);
                *(__nv_bfloat162*)(g_ahi + (ra + 8) * E_ + col) = __halves2bfloat162(p2, p3);
                *(__nv_bfloat162*)(g_alo + ra * E_ + col) =
                    __halves2bfloat162(__float2bfloat16(a0 - __bfloat162float(p0)),
                                       __float2bfloat16(a1 - __bfloat162float(p1)));
                *(__nv_bfloat162*)(g_alo + (ra + 8) * E_ + col) =
                    __halves2bfloat162(__float2bfloat16(a2 - __bfloat162float(p2)),
                                       __float2bfloat16(a3 - __bfloat162float(p3)));
            }
            if constexpr (MODE == 2) {
                ps[ni][0] += o0 + o2;
                ps[ni][1] += o1 + o3;
            }
        }
    }

    if constexpr (MODE == 2) {
#pragma unroll
        for (int ni = 0; ni < 8; ni++)
#pragma unroll
            for (int o = 4; o <= 16; o <<= 1) {
                ps[ni][0] += __shfl_xor_sync(0xffffffffu, ps[ni][0], o);
                ps[ni][1] += __shfl_xor_sync(0xffffffffu, ps[ni][1], o);
            }
        if (lane < 4) {
#pragma unroll
            for (int ni = 0; ni < 8; ni++) {
                pps[wm * 256 + mcol + ni * 8]     = ps[ni][0];
                pps[wm * 256 + mcol + ni * 8 + 1] = ps[ni][1];
            }
        }
        __syncthreads();
        if (tid < 256) g_pp[blockIdx.x * 256 + tid] = pps[tid] + pps[256 + tid];
    }
}

// ---------------- classifier -------------------------------------------------
__global__ void k_cls(const float* __restrict__ w, const float* __restrict__ cb,
                      float* __restrict__ out) {
    __shared__ float sh[16];
    int b = blockIdx.x, e = threadIdx.x;
    float p = 0.f;
#pragma unroll 8
    for (int j = 0; j < 32; j++) p += g_pp[(b * 32 + j) * E_ + e];
    p *= (1.0f / (float)S_);
    float s0 = p * w[e * 2], s1 = p * w[e * 2 + 1];
    for (int o = 16; o > 0; o >>= 1) {
        s0 += __shfl_xor_sync(0xffffffffu, s0, o);
        s1 += __shfl_xor_sync(0xffffffffu, s1, o);
    }
    int wi = e >> 5;
    if ((e & 31) == 0) { sh[wi * 2] = s0; sh[wi * 2 + 1] = s1; }
    __syncthreads();
    if (e == 0) {
        float t0 = 0, t1 = 0;
#pragma unroll
        for (int j = 0; j < 8; j++) { t0 += sh[j * 2]; t1 += sh[j * 2 + 1]; }
        out[b * 2]     = t0 + cb[0];
        out[b * 2 + 1] = t1 + cb[1];
    }
}

// ---------------- host launcher ----------------------------------------------
extern "C" void kernel_launch(void* const* d_in, const int* in_sizes, int n_in,
                              void* d_out, int out_size) {
    const int*   tokens     = (const int*)d_in[0];
    const float* embed      = (const float*)d_in[1];
    const float* attn_theta = (const float*)d_in[2];
    const float* combine_w  = (const float*)d_in[3];
    const float* combine_b  = (const float*)d_in[4];
    const float* ffn_theta  = (const float*)d_in[5];
    const float* lin1_w     = (const float*)d_in[6];
    const float* lin1_b     = (const float*)d_in[7];
    const float* lin2_w     = (const float*)d_in[8];
    const float* lin2_b     = (const float*)d_in[9];
    const float* ln1_g      = (const float*)d_in[10];
    const float* ln1_b      = (const float*)d_in[11];
    const float* ln2_g      = (const float*)d_in[12];
    const float* ln2_b      = (const float*)d_in[13];
    const float* cls_w      = (const float*)d_in[14];
    const float* cls_b      = (const float*)d_in[15];
    float* out = (float*)d_out;

    __nv_bfloat16 *ahi, *alo, *whi, *wlo;
    float *qp;
    cudaGetSymbolAddress((void**)&ahi, g_ahi);
    cudaGetSymbolAddress((void**)&alo, g_alo);
    cudaGetSymbolAddress((void**)&whi, g_whi);
    cudaGetSymbolAddress((void**)&wlo, g_wlo);
    cudaGetSymbolAddress((void**)&qp,  g_q);

    cudaFuncSetAttribute(k_gf<256, 0, false>, cudaFuncAttributeMaxDynamicSharedMemorySize, SME_ATT);
    cudaFuncSetAttribute(k_gf<512, 1, true>,  cudaFuncAttributeMaxDynamicSharedMemorySize, SME_FFN);
    cudaFuncSetAttribute(k_gf<512, 2, true>,  cudaFuncAttributeMaxDynamicSharedMemorySize, SME_FFN);

    k_embed<<<M_, 256>>>(tokens, embed, attn_theta);
    k_convw<<<dim3(256, 4), 256>>>(combine_w, lin2_w);

    // layer 0
    k_gf<256, 0, false><<<M_ / 64, 256, SME_ATT>>>(
        ahi, alo, whi + 0 * 131072, wlo + 0 * 131072, combine_b + 0 * E_,
        ln1_g + 0 * E_, ln1_b + 0 * E_, nullptr,
        ffn_theta + 0 * NQ_, nullptr, nullptr, nullptr);
    k_gf<512, 1, true><<<M_ / 64, 256, SME_FFN>>>(
        nullptr, nullptr, whi + 2 * 131072, wlo + 2 * 131072, lin2_b + 0 * E_,
        ln2_g + 0 * E_, ln2_b + 0 * E_, attn_theta + 1 * 64,
        nullptr, qp, lin1_w + 0 * NQ_ * FFN_, lin1_b + 0 * FFN_);
    // layer 1
    k_gf<256, 0, false><<<M_ / 64, 256, SME_ATT>>>(
        ahi, alo, whi + 1 * 131072, wlo + 1 * 131072, combine_b + 1 * E_,
        ln1_g + 1 * E_, ln1_b + 1 * E_, nullptr,
        ffn_theta + 1 * NQ_, nullptr, nullptr, nullptr);
    k_gf<512, 2, true><<<M_ / 64, 256, SME_FFN>>>(
        nullptr, nullptr, whi + 3 * 131072, wlo + 3 * 131072, lin2_b + 1 * E_,
        ln2_g + 1 * E_, ln2_b + 1 * E_, nullptr,
        nullptr, qp, lin1_w + 1 * NQ_ * FFN_, lin1_b + 1 * FFN_);

    k_cls<<<B_, 256>>>(cls_w, cls_b, out);
}

// round 7
// speedup vs baseline: 3.2574x; 1.2212x over previous
#include <cuda_runtime.h>
#include <cuda_fp16.h>
#include <cstdint>
#include <math.h>

#define B_   16
#define S_   2048
#define E_   256
#define L_   2
#define NQ_  8
#define FFN_ 512
#define C_   2
#define M_   (B_*S_)   // 32768 rows

// ---------------- scratch (__device__ globals; no allocations) ---------------
__device__ float g_x[(size_t)M_*E_];                      // 32 MB
__device__ float g_q[(size_t)M_*NQ_];                     // 1 MB
__device__ __align__(128) __half g_ahi[(size_t)M_*E_];    // 16 MB
__device__ __align__(128) __half g_alo[(size_t)M_*E_];    // 16 MB
__device__ __align__(128) __half g_wh[4*256*512];         // Wt[n][k] fp16
__device__ float g_pp[512*E_];                            // pool partials

// ---------------- PTX helpers ------------------------------------------------
__device__ __forceinline__ uint32_t s2u(const void* p) {
    uint32_t a;
    asm("{ .reg .u64 t; cvta.to.shared.u64 t, %1; cvt.u32.u64 %0, t; }"
        : "=r"(a) : "l"(p));
    return a;
}
__device__ __forceinline__ void cp16(uint32_t dst, const void* src) {
    asm volatile("cp.async.cg.shared.global [%0], [%1], 16;" :: "r"(dst), "l"(src));
}
__device__ __forceinline__ void cp_commit() {
    asm volatile("cp.async.commit_group;" ::: "memory");
}
__device__ __forceinline__ void cp_wait1() {
    asm volatile("cp.async.wait_group 1;" ::: "memory");
}
__device__ __forceinline__ void cp_wait0() {
    asm volatile("cp.async.wait_group 0;" ::: "memory");
}
__device__ __forceinline__ void ldm_x4(uint32_t& r0, uint32_t& r1, uint32_t& r2,
                                       uint32_t& r3, uint32_t addr) {
    asm volatile("ldmatrix.sync.aligned.m8n8.x4.shared.b16 {%0,%1,%2,%3}, [%4];"
                 : "=r"(r0), "=r"(r1), "=r"(r2), "=r"(r3) : "r"(addr));
}
__device__ __forceinline__ void ldm_x2(uint32_t& r0, uint32_t& r1, uint32_t addr) {
    asm volatile("ldmatrix.sync.aligned.m8n8.x2.shared.b16 {%0,%1}, [%2];"
                 : "=r"(r0), "=r"(r1) : "r"(addr));
}
__device__ __forceinline__ void mma16816(float* c, uint32_t a0, uint32_t a1,
                                         uint32_t a2, uint32_t a3,
                                         uint32_t b0, uint32_t b1) {
    asm volatile(
        "mma.sync.aligned.m16n8k16.row.col.f32.f16.f16.f32 "
        "{%0,%1,%2,%3}, {%4,%5,%6,%7}, {%8,%9}, {%0,%1,%2,%3};"
        : "+f"(c[0]), "+f"(c[1]), "+f"(c[2]), "+f"(c[3])
        : "r"(a0), "r"(a1), "r"(a2), "r"(a3), "r"(b0), "r"(b1));
}

// ---------------- embed + PE + fused prep for layer-0 attn -------------------
__global__ void k_embed(const int* __restrict__ tok, const float* __restrict__ emb,
                        const float* __restrict__ th) {
    int row = blockIdx.x;
    int e   = threadIdx.x;
    int t   = tok[row];
    int s   = row & (S_ - 1);
    int i   = e >> 1;
    float freq = expf(-(float)(2 * i) * (9.210340371976184f / (float)E_));
    float ang  = (float)s * freq;
    float pe   = (e & 1) ? cosf(ang) : sinf(ang);
    size_t idx = (size_t)row * E_ + e;
    float x = emb[(size_t)t * E_ + e] + pe;
    g_x[idx] = x;
    float a = cosf(x + th[e & 63]);
    __half hi = __float2half_rn(a);
    g_ahi[idx] = hi;
    g_alo[idx] = __float2half_rn(a - __half2float(hi));
}

// ---------------- weight convert + transpose (fp16 hi only) ------------------
__global__ void k_convw(const float* __restrict__ cw, const float* __restrict__ l2w) {
    int slot = blockIdx.y;
    int n    = blockIdx.x;
    int K    = (slot < 2) ? 256 : 512;
    const float* src = (slot < 2) ? (cw + (size_t)slot * E_ * E_)
                                  : (l2w + (size_t)(slot - 2) * FFN_ * E_);
    for (int k = threadIdx.x; k < K; k += 256) {
        float w = src[(size_t)k * E_ + n];
        g_wh[(size_t)slot * 131072 + (size_t)n * K + k] = __float2half_rn(w);
    }
}

// ---------------- fused GEMM (2-term fp16) + LN + producers ------------------
// BM=64, BN=256, BK=32, 256 threads (2M x 4N warps, warp tile 32x64).
// D = Ah*Wh + Al*Wh (A split fp16, W single fp16). 64B rows + XOR swizzle.
// 3-stage cp.async pipeline, 2 CTAs/SM.
#define A_HI_O  0
#define A_LO_O  4096
#define W_HI_O  8192
#define STAGE   24576
#define Q_OFF   (3*STAGE)            // 73728, 2048 B
#define W1_OFF  (Q_OFF + 2048)       // 18432 B (512 x 9 floats)
#define B1_OFF  (W1_OFF + 18432)     // 2048 B
#define SME_ATT (3*STAGE)            // 73728
#define SME_FFN (B1_OFF + 2048)      // 96256

template <int K, int MODE, bool COMPA>
__global__ void __launch_bounds__(256, 2)
k_gf(const __half* __restrict__ Agh, const __half* __restrict__ Agl,
     const __half* __restrict__ Whi,
     const float* __restrict__ bias,
     const float* __restrict__ lnG, const float* __restrict__ lnB,
     const float* __restrict__ thN,                       // MODE 1
     const float* __restrict__ fTh,                       // MODE 0
     const float* __restrict__ qg, const float* __restrict__ W1,
     const float* __restrict__ b1) {                      // COMPA
    constexpr int CH = K >> 5;
    extern __shared__ __align__(16) char smem[];
    uint32_t sb = s2u(smem);
    int tid = threadIdx.x, lane = tid & 31, wid = tid >> 5;
    int wm = wid >> 2, wn = wid & 3;
    size_t bm = (size_t)blockIdx.x * 64;

    float* qsh = (float*)(smem + Q_OFF);
    float* w1t = (float*)(smem + W1_OFF);
    float* b1s = (float*)(smem + B1_OFF);

    if constexpr (COMPA) {
        for (int i = tid; i < 512; i += 256) qsh[i] = qg[bm * 8 + i];
        for (int i = tid; i < 4096; i += 256) {
            int f = i >> 3, n = i & 7;
            w1t[f * 9 + n] = W1[n * FFN_ + f];
        }
        for (int i = tid; i < 512; i += 256) b1s[i] = b1[i];
        __syncthreads();
    }

    float acc[2][8][4];
#pragma unroll
    for (int i = 0; i < 2; i++)
#pragma unroll
        for (int j = 0; j < 8; j++)
#pragma unroll
            for (int c = 0; c < 4; c++) acc[i][j][c] = 0.f;

    int part = tid & 3, rb = tid >> 2;               // rb 0..63
    uint32_t swc = (uint32_t)(part ^ ((rb >> 1) & 3)) << 4;

    auto load_stage = [&](int st, int ch) {
        uint32_t dst = sb + st * STAGE;
        int kk = ch << 5;
        if constexpr (!COMPA) {
            cp16(dst + A_HI_O + rb * 64 + swc,
                 Agh + (bm + rb) * (size_t)K + kk + part * 8);
            cp16(dst + A_LO_O + rb * 64 + swc,
                 Agl + (bm + rb) * (size_t)K + kk + part * 8);
        }
#pragma unroll
        for (int i = 0; i < 4; i++) {
            int r = rb + i * 64;
            cp16(dst + W_HI_O + r * 64 + swc, Whi + (size_t)r * K + kk + part * 8);
        }
        cp_commit();
    };

    auto comp_a = [&](int st, int ch) {
        char* dst = smem + st * STAGE;
        int r = rb, f0 = (ch << 5) + part * 8;
        float qr[8];
#pragma unroll
        for (int n = 0; n < 8; n++) qr[n] = qsh[r * 8 + n];
        __half2 hp[4], lp[4];
#pragma unroll
        for (int jj = 0; jj < 4; jj++) {
            float hv[2];
#pragma unroll
            for (int u = 0; u < 2; u++) {
                int f = f0 + jj * 2 + u;
                float h = b1s[f];
#pragma unroll
                for (int n = 0; n < 8; n++) h += qr[n] * w1t[f * 9 + n];
                hv[u] = fmaxf(h, 0.f);
            }
            __half p0 = __float2half_rn(hv[0]);
            __half p1 = __float2half_rn(hv[1]);
            hp[jj] = __halves2half2(p0, p1);
            lp[jj] = __halves2half2(__float2half_rn(hv[0] - __half2float(p0)),
                                    __float2half_rn(hv[1] - __half2float(p1)));
        }
        *(uint4*)(dst + A_HI_O + r * 64 + swc) = *(uint4*)hp;
        *(uint4*)(dst + A_LO_O + r * 64 + swc) = *(uint4*)lp;
    };

    load_stage(0, 0);
    if constexpr (COMPA) comp_a(0, 0);
    if (CH > 1) {
        load_stage(1, 1);
        if constexpr (COMPA) comp_a(1, 1);
    }

    uint32_t sxA = (((uint32_t)lane & 15) >> 1) & 3;
    uint32_t sxB = (((uint32_t)lane & 7) >> 1) & 3;
    uint32_t cA  = (uint32_t)lane >> 4;
    uint32_t cB  = ((uint32_t)lane >> 3) & 1;
    uint32_t rowA = (wm * 32 + (lane & 15)) * 64;
    uint32_t rowB = (wn * 64 + (lane & 7)) * 64;

    for (int cc = 0; cc < CH; cc++) {
        if (cc + 1 < CH) cp_wait1(); else cp_wait0();
        __syncthreads();
        if (cc + 2 < CH) {
            load_stage((cc + 2) % 3, cc + 2);
            if constexpr (COMPA) comp_a((cc + 2) % 3, cc + 2);
        }
        uint32_t stg = sb + (cc % 3) * STAGE;

#pragma unroll
        for (int kb = 0; kb < 2; kb++) {
            uint32_t colA = ((kb * 2 + cA) ^ sxA) << 4;
            uint32_t colB = ((kb * 2 + cB) ^ sxB) << 4;
            uint32_t b0[8], b1r[8];
#pragma unroll
            for (int ni = 0; ni < 8; ni++)
                ldm_x2(b0[ni], b1r[ni], stg + W_HI_O + rowB + ni * 512 + colB);
            uint32_t h0[2], h1[2], h2[2], h3[2];
#pragma unroll
            for (int mi = 0; mi < 2; mi++)
                ldm_x4(h0[mi], h1[mi], h2[mi], h3[mi],
                       stg + A_HI_O + rowA + mi * 1024 + colA);
#pragma unroll
            for (int mi = 0; mi < 2; mi++)
#pragma unroll
                for (int ni = 0; ni < 8; ni++)
                    mma16816(acc[mi][ni], h0[mi], h1[mi], h2[mi], h3[mi], b0[ni], b1r[ni]);
            uint32_t l0[2], l1[2], l2[2], l3[2];
#pragma unroll
            for (int mi = 0; mi < 2; mi++)
                ldm_x4(l0[mi], l1[mi], l2[mi], l3[mi],
                       stg + A_LO_O + rowA + mi * 1024 + colA);
#pragma unroll
            for (int mi = 0; mi < 2; mi++)
#pragma unroll
                for (int ni = 0; ni < 8; ni++)
                    mma16816(acc[mi][ni], l0[mi], l1[mi], l2[mi], l3[mi], b0[ni], b1r[ni]);
        }
    }
    __syncthreads();

    // ---------- epilogue: residual + LayerNorm (+ producers) ----------
    float2* red = (float2*)smem;                  // [64][4]
    float2* mr  = (float2*)(smem + 2048);         // [64]
    float*  pps = (float*)(smem + 4096);          // [2][256] (MODE 2)

    int mcol = wn * 64 + (lane & 3) * 2;
    int r0l  = wm * 32 + (lane >> 2);

#pragma unroll
    for (int mi = 0; mi < 2; mi++) {
        float s0 = 0, q0 = 0, s1 = 0, q1 = 0;
        size_t ra = bm + r0l + mi * 16;
#pragma unroll
        for (int ni = 0; ni < 8; ni++) {
            int col = mcol + ni * 8;
            float2 x0 = *(const float2*)(g_x + ra * E_ + col);
            float2 x1 = *(const float2*)(g_x + (ra + 8) * E_ + col);
            float bcx = bias[col], bcy = bias[col + 1];
            float v0 = acc[mi][ni][0] + bcx + x0.x;
            float v1 = acc[mi][ni][1] + bcy + x0.y;
            float v2 = acc[mi][ni][2] + bcx + x1.x;
            float v3 = acc[mi][ni][3] + bcy + x1.y;
            acc[mi][ni][0] = v0; acc[mi][ni][1] = v1;
            acc[mi][ni][2] = v2; acc[mi][ni][3] = v3;
            s0 += v0 + v1; q0 += v0 * v0 + v1 * v1;
            s1 += v2 + v3; q1 += v2 * v2 + v3 * v3;
        }
#pragma unroll
        for (int o = 1; o <= 2; o <<= 1) {
            s0 += __shfl_xor_sync(0xffffffffu, s0, o);
            q0 += __shfl_xor_sync(0xffffffffu, q0, o);
            s1 += __shfl_xor_sync(0xffffffffu, s1, o);
            q1 += __shfl_xor_sync(0xffffffffu, q1, o);
        }
        if ((lane & 3) == 0) {
            int rl = r0l + mi * 16;
            red[rl * 4 + wn] = make_float2(s0, q0);
            red[(rl + 8) * 4 + wn] = make_float2(s1, q1);
        }
    }
    __syncthreads();
    if (tid < 64) {
        float s = 0, q = 0;
#pragma unroll
        for (int j = 0; j < 4; j++) { float2 t = red[tid * 4 + j]; s += t.x; q += t.y; }
        float mean = s * (1.0f / E_);
        float var  = q * (1.0f / E_) - mean * mean;
        mr[tid] = make_float2(mean, rsqrtf(var + 1e-5f));
    }
    __syncthreads();

    float cf0 = 0.f, cf1 = 0.f;
    if constexpr (MODE == 0) {
        int c = (lane & 3) * 2;
        cf0 = cosf(fTh[c]); cf1 = cosf(fTh[c + 1]);
    }
    float ps[8][2];
    if constexpr (MODE == 2) {
#pragma unroll
        for (int ni = 0; ni < 8; ni++) { ps[ni][0] = 0.f; ps[ni][1] = 0.f; }
    }

#pragma unroll
    for (int mi = 0; mi < 2; mi++) {
        int rl = r0l + mi * 16;
        float2 m0 = mr[rl], m1 = mr[rl + 8];
        size_t ra = bm + rl;
#pragma unroll
        for (int ni = 0; ni < 8; ni++) {
            int col = mcol + ni * 8;
            float gx = lnG[col], gy = lnG[col + 1];
            float bx = lnB[col], by = lnB[col + 1];
            float o0 = (acc[mi][ni][0] - m0.x) * m0.y * gx + bx;
            float o1 = (acc[mi][ni][1] - m0.x) * m0.y * gy + by;
            float o2 = (acc[mi][ni][2] - m1.x) * m1.y * gx + bx;
            float o3 = (acc[mi][ni][3] - m1.x) * m1.y * gy + by;
            if constexpr (MODE != 2) {
                *(float2*)(g_x + ra * E_ + col) = make_float2(o0, o1);
                *(float2*)(g_x + (ra + 8) * E_ + col) = make_float2(o2, o3);
            }
            if constexpr (MODE == 0) {
                if (wn == 0 && ni == 0) {
                    int c = (lane & 3) * 2;
                    g_q[ra * 8 + c]           = cosf(o0) * cf0;
                    g_q[ra * 8 + c + 1]       = cosf(o1) * cf1;
                    g_q[(ra + 8) * 8 + c]     = cosf(o2) * cf0;
                    g_q[(ra + 8) * 8 + c + 1] = cosf(o3) * cf1;
                }
            }
            if constexpr (MODE == 1) {
                float t0 = thN[col & 63], t1 = thN[(col + 1) & 63];
                float a0 = cosf(o0 + t0), a1 = cosf(o1 + t1);
                float a2 = cosf(o2 + t0), a3 = cosf(o3 + t1);
                __half p0 = __float2half_rn(a0), p1 = __float2half_rn(a1);
                __half p2 = __float2half_rn(a2), p3 = __float2half_rn(a3);
                *(__half2*)(g_ahi + ra * E_ + col) = __halves2half2(p0, p1);
                *(__half2*)(g_ahi + (ra + 8) * E_ + col) = __halves2half2(p2, p3);
                *(__half2*)(g_alo + ra * E_ + col) =
                    __halves2half2(__float2half_rn(a0 - __half2float(p0)),
                                   __float2half_rn(a1 - __half2float(p1)));
                *(__half2*)(g_alo + (ra + 8) * E_ + col) =
                    __halves2half2(__float2half_rn(a2 - __half2float(p2)),
                                   __float2half_rn(a3 - __half2float(p3)));
            }
            if constexpr (MODE == 2) {
                ps[ni][0] += o0 + o2;
                ps[ni][1] += o1 + o3;
            }
        }
    }

    if constexpr (MODE == 2) {
#pragma unroll
        for (int ni = 0; ni < 8; ni++)
#pragma unroll
            for (int o = 4; o <= 16; o <<= 1) {
                ps[ni][0] += __shfl_xor_sync(0xffffffffu, ps[ni][0], o);
                ps[ni][1] += __shfl_xor_sync(0xffffffffu, ps[ni][1], o);
            }
        if (lane < 4) {
#pragma unroll
            for (int ni = 0; ni < 8; ni++) {
                pps[wm * 256 + mcol + ni * 8]     = ps[ni][0];
                pps[wm * 256 + mcol + ni * 8 + 1] = ps[ni][1];
            }
        }
        __syncthreads();
        if (tid < 256) g_pp[blockIdx.x * 256 + tid] = pps[tid] + pps[256 + tid];
    }
}

// ---------------- classifier -------------------------------------------------
__global__ void k_cls(const float* __restrict__ w, const float* __restrict__ cb,
                      float* __restrict__ out) {
    __shared__ float sh[16];
    int b = blockIdx.x, e = threadIdx.x;
    float p = 0.f;
#pragma unroll 8
    for (int j = 0; j < 32; j++) p += g_pp[(b * 32 + j) * E_ + e];
    p *= (1.0f / (float)S_);
    float s0 = p * w[e * 2], s1 = p * w[e * 2 + 1];
    for (int o = 16; o > 0; o >>= 1) {
        s0 += __shfl_xor_sync(0xffffffffu, s0, o);
        s1 += __shfl_xor_sync(0xffffffffu, s1, o);
    }
    int wi = e >> 5;
    if ((e & 31) == 0) { sh[wi * 2] = s0; sh[wi * 2 + 1] = s1; }
    __syncthreads();
    if (e == 0) {
        float t0 = 0, t1 = 0;
#pragma unroll
        for (int j = 0; j < 8; j++) { t0 += sh[j * 2]; t1 += sh[j * 2 + 1]; }
        out[b * 2]     = t0 + cb[0];
        out[b * 2 + 1] = t1 + cb[1];
    }
}

// ---------------- host launcher ----------------------------------------------
extern "C" void kernel_launch(void* const* d_in, const int* in_sizes, int n_in,
                              void* d_out, int out_size) {
    const int*   tokens     = (const int*)d_in[0];
    const float* embed      = (const float*)d_in[1];
    const float* attn_theta = (const float*)d_in[2];
    const float* combine_w  = (const float*)d_in[3];
    const float* combine_b  = (const float*)d_in[4];
    const float* ffn_theta  = (const float*)d_in[5];
    const float* lin1_w     = (const float*)d_in[6];
    const float* lin1_b     = (const float*)d_in[7];
    const float* lin2_w     = (const float*)d_in[8];
    const float* lin2_b     = (const float*)d_in[9];
    const float* ln1_g      = (const float*)d_in[10];
    const float* ln1_b      = (const float*)d_in[11];
    const float* ln2_g      = (const float*)d_in[12];
    const float* ln2_b      = (const float*)d_in[13];
    const float* cls_w      = (const float*)d_in[14];
    const float* cls_b      = (const float*)d_in[15];
    float* out = (float*)d_out;

    __half *ahi, *alo, *wh;
    float *qp;
    cudaGetSymbolAddress((void**)&ahi, g_ahi);
    cudaGetSymbolAddress((void**)&alo, g_alo);
    cudaGetSymbolAddress((void**)&wh,  g_wh);
    cudaGetSymbolAddress((void**)&qp,  g_q);

    cudaFuncSetAttribute(k_gf<256, 0, false>, cudaFuncAttributeMaxDynamicSharedMemorySize, SME_ATT);
    cudaFuncSetAttribute(k_gf<512, 1, true>,  cudaFuncAttributeMaxDynamicSharedMemorySize, SME_FFN);
    cudaFuncSetAttribute(k_gf<512, 2, true>,  cudaFuncAttributeMaxDynamicSharedMemorySize, SME_FFN);

    k_embed<<<M_, 256>>>(tokens, embed, attn_theta);
    k_convw<<<dim3(256, 4), 256>>>(combine_w, lin2_w);

    // layer 0
    k_gf<256, 0, false><<<M_ / 64, 256, SME_ATT>>>(
        ahi, alo, wh + 0 * 131072, combine_b + 0 * E_,
        ln1_g + 0 * E_, ln1_b + 0 * E_, nullptr,
        ffn_theta + 0 * NQ_, nullptr, nullptr, nullptr);
    k_gf<512, 1, true><<<M_ / 64, 256, SME_FFN>>>(
        nullptr, nullptr, wh + 2 * 131072, lin2_b + 0 * E_,
        ln2_g + 0 * E_, ln2_b + 0 * E_, attn_theta + 1 * 64,
        nullptr, qp, lin1_w + 0 * NQ_ * FFN_, lin1_b + 0 * FFN_);
    // layer 1
    k_gf<256, 0, false><<<M_ / 64, 256, SME_ATT>>>(
        ahi, alo, wh + 1 * 131072, combine_b + 1 * E_,
        ln1_g + 1 * E_, ln1_b + 1 * E_, nullptr,
        ffn_theta + 1 * NQ_, nullptr, nullptr, nullptr);
    k_gf<512, 2, true><<<M_ / 64, 256, SME_FFN>>>(
        nullptr, nullptr, wh + 3 * 131072, lin2_b + 1 * E_,
        ln2_g + 1 * E_, ln2_b + 1 * E_, nullptr,
        nullptr, qp, lin1_w + 1 * NQ_ * FFN_, lin1_b + 1 * FFN_);

    k_cls<<<B_, 256>>>(cls_w, cls_b, out);
}

// round 8
// speedup vs baseline: 3.4689x; 1.0649x over previous
#include <cuda_runtime.h>
#include <cuda_fp16.h>
#include <cstdint>
#include <math.h>

#define B_   16
#define S_   2048
#define E_   256
#define L_   2
#define NQ_  8
#define FFN_ 512
#define C_   2
#define M_   (B_*S_)   // 32768 rows

// ---------------- scratch (__device__ globals; no allocations) ---------------
__device__ float g_x[(size_t)M_*E_];                      // 32 MB
__device__ float g_q[(size_t)M_*NQ_];                     // 1 MB
__device__ __align__(128) __half g_ahi[(size_t)M_*E_];    // 16 MB
__device__ __align__(128) __half g_alo[(size_t)M_*E_];    // 16 MB
__device__ __align__(128) __half g_wh[4*256*512];         // Wt[n][k] fp16
__device__ float g_pp[512*E_];                            // pool partials

// ---------------- PTX helpers ------------------------------------------------
__device__ __forceinline__ uint32_t s2u(const void* p) {
    uint32_t a;
    asm("{ .reg .u64 t; cvta.to.shared.u64 t, %1; cvt.u32.u64 %0, t; }"
        : "=r"(a) : "l"(p));
    return a;
}
__device__ __forceinline__ void cp16(uint32_t dst, const void* src) {
    asm volatile("cp.async.cg.shared.global [%0], [%1], 16;" :: "r"(dst), "l"(src));
}
__device__ __forceinline__ void cp_commit() {
    asm volatile("cp.async.commit_group;" ::: "memory");
}
__device__ __forceinline__ void cp_wait1() {
    asm volatile("cp.async.wait_group 1;" ::: "memory");
}
__device__ __forceinline__ void cp_wait0() {
    asm volatile("cp.async.wait_group 0;" ::: "memory");
}
__device__ __forceinline__ void ldm_x4(uint32_t& r0, uint32_t& r1, uint32_t& r2,
                                       uint32_t& r3, uint32_t addr) {
    asm volatile("ldmatrix.sync.aligned.m8n8.x4.shared.b16 {%0,%1,%2,%3}, [%4];"
                 : "=r"(r0), "=r"(r1), "=r"(r2), "=r"(r3) : "r"(addr));
}
__device__ __forceinline__ void mma16816(float* c, uint32_t a0, uint32_t a1,
                                         uint32_t a2, uint32_t a3,
                                         uint32_t b0, uint32_t b1) {
    asm volatile(
        "mma.sync.aligned.m16n8k16.row.col.f32.f16.f16.f32 "
        "{%0,%1,%2,%3}, {%4,%5,%6,%7}, {%8,%9}, {%0,%1,%2,%3};"
        : "+f"(c[0]), "+f"(c[1]), "+f"(c[2]), "+f"(c[3])
        : "r"(a0), "r"(a1), "r"(a2), "r"(a3), "r"(b0), "r"(b1));
}

// ---------------- embed + PE + fused prep for layer-0 attn -------------------
__global__ void k_embed(const int* __restrict__ tok, const float* __restrict__ emb,
                        const float* __restrict__ th) {
    int row = blockIdx.x;
    int e   = threadIdx.x;
    int t   = tok[row];
    int s   = row & (S_ - 1);
    int i   = e >> 1;
    float freq = expf(-(float)(2 * i) * (9.210340371976184f / (float)E_));
    float ang  = (float)s * freq;
    float pe   = (e & 1) ? cosf(ang) : sinf(ang);
    size_t idx = (size_t)row * E_ + e;
    float x = emb[(size_t)t * E_ + e] + pe;
    g_x[idx] = x;
    float a = cosf(x + th[e & 63]);
    __half hi = __float2half_rn(a);
    g_ahi[idx] = hi;
    g_alo[idx] = __float2half_rn(a - __half2float(hi));
}

// ---------------- weight convert + transpose (fp16) --------------------------
__global__ void k_convw(const float* __restrict__ cw, const float* __restrict__ l2w) {
    int slot = blockIdx.y;
    int n    = blockIdx.x;
    int K    = (slot < 2) ? 256 : 512;
    const float* src = (slot < 2) ? (cw + (size_t)slot * E_ * E_)
                                  : (l2w + (size_t)(slot - 2) * FFN_ * E_);
    for (int k = threadIdx.x; k < K; k += 256) {
        float w = src[(size_t)k * E_ + n];
        g_wh[(size_t)slot * 131072 + (size_t)n * K + k] = __float2half_rn(w);
    }
}

// ---------------- fused GEMM (2-term fp16, BK=64) + LN + producers -----------
// BM=64, BN=256, BK=64 (128B rows, XOR-8 swizzle), 256 threads (2Mx4N warps).
// 2-stage double buffer, 2 CTAs/SM. B fragments via ldmatrix.x4 (ni pairs).
#define A_HI_O  0
#define A_LO_O  8192
#define W_O     16384
#define STAGE   49152
#define Q_OFF   (2*STAGE)            // 98304, 2048 B (floats)
#define W1_OFF  (Q_OFF + 2048)       // 9216 B (512 x 9 halves)
#define B1_OFF  (W1_OFF + 9216)      // 2048 B (floats)
#define SME_ATT (2*STAGE)            // 98304
#define SME_FFN (B1_OFF + 2048)      // 111616

template <int K, int MODE, bool COMPA>
__global__ void __launch_bounds__(256, 2)
k_gf(const __half* __restrict__ Agh, const __half* __restrict__ Agl,
     const __half* __restrict__ Whi,
     const float* __restrict__ bias,
     const float* __restrict__ lnG, const float* __restrict__ lnB,
     const float* __restrict__ thN,                       // MODE 1
     const float* __restrict__ fTh,                       // MODE 0
     const float* __restrict__ qg, const float* __restrict__ W1,
     const float* __restrict__ b1) {                      // COMPA
    constexpr int CH = K >> 6;
    extern __shared__ __align__(16) char smem[];
    uint32_t sb = s2u(smem);
    int tid = threadIdx.x, lane = tid & 31, wid = tid >> 5;
    int wm = wid >> 2, wn = wid & 3;
    size_t bm = (size_t)blockIdx.x * 64;

    float*  qsh = (float*)(smem + Q_OFF);
    __half* w1h = (__half*)(smem + W1_OFF);
    float*  b1s = (float*)(smem + B1_OFF);

    if constexpr (COMPA) {
        for (int i = tid; i < 512; i += 256) qsh[i] = qg[bm * 8 + i];
        for (int i = tid; i < 4096; i += 256) {
            int f = i >> 3, n = i & 7;
            w1h[f * 9 + n] = __float2half_rn(W1[n * FFN_ + f]);
        }
        for (int i = tid; i < 512; i += 256) b1s[i] = b1[i];
        __syncthreads();
    }

    float acc[2][8][4];
#pragma unroll
    for (int i = 0; i < 2; i++)
#pragma unroll
        for (int j = 0; j < 8; j++)
#pragma unroll
            for (int c = 0; c < 4; c++) acc[i][j][c] = 0.f;

    int part = tid & 7, rbase = tid >> 3;                  // rbase 0..31
    uint32_t swc = (uint32_t)(part ^ (rbase & 7)) << 4;

    auto load_stage = [&](int st, int ch) {
        uint32_t dst = sb + st * STAGE;
        int kk = ch << 6;
        if constexpr (!COMPA) {
#pragma unroll
            for (int i = 0; i < 2; i++) {
                int r = rbase + i * 32;
                cp16(dst + A_HI_O + r * 128 + swc,
                     Agh + (bm + r) * (size_t)K + kk + part * 8);
                cp16(dst + A_LO_O + r * 128 + swc,
                     Agl + (bm + r) * (size_t)K + kk + part * 8);
            }
        }
#pragma unroll
        for (int i = 0; i < 8; i++) {
            int r = rbase + i * 32;
            cp16(dst + W_O + r * 128 + swc, Whi + (size_t)r * K + kk + part * 8);
        }
        cp_commit();
    };

    auto comp_a = [&](int st, int ch) {
        char* dst = smem + st * STAGE;
        int r = tid >> 2, cg = tid & 3;
        int f0 = (ch << 6) + cg * 16;
        float qr[8];
#pragma unroll
        for (int n = 0; n < 8; n++) qr[n] = qsh[r * 8 + n];
        __half2 hp[8], lp[8];
#pragma unroll
        for (int jj = 0; jj < 8; jj++) {
            float hv[2];
#pragma unroll
            for (int u = 0; u < 2; u++) {
                int f = f0 + jj * 2 + u;
                float h = b1s[f];
#pragma unroll
                for (int n = 0; n < 8; n++)
                    h += qr[n] * __half2float(w1h[f * 9 + n]);
                hv[u] = fmaxf(h, 0.f);
            }
            __half p0 = __float2half_rn(hv[0]);
            __half p1 = __float2half_rn(hv[1]);
            hp[jj] = __halves2half2(p0, p1);
            lp[jj] = __halves2half2(__float2half_rn(hv[0] - __half2float(p0)),
                                    __float2half_rn(hv[1] - __half2float(p1)));
        }
        uint32_t o0 = (uint32_t)r * 128 + ((((uint32_t)cg * 2)     ^ (r & 7)) << 4);
        uint32_t o1 = (uint32_t)r * 128 + ((((uint32_t)cg * 2 + 1) ^ (r & 7)) << 4);
        *(uint4*)(dst + A_HI_O + o0) = *(uint4*)&hp[0];
        *(uint4*)(dst + A_HI_O + o1) = *(uint4*)&hp[4];
        *(uint4*)(dst + A_LO_O + o0) = *(uint4*)&lp[0];
        *(uint4*)(dst + A_LO_O + o1) = *(uint4*)&lp[4];
    };

    load_stage(0, 0);
    if constexpr (COMPA) comp_a(0, 0);
    load_stage(1, 1);
    if constexpr (COMPA) comp_a(1, 1);

    uint32_t rowA = wm * 32 + (lane & 15);
    uint32_t rxA  = rowA & 7;
    uint32_t cA   = (uint32_t)lane >> 4;                   // 0..1
    uint32_t rowB = wn * 64 + ((lane >> 4) & 1) * 8 + (lane & 7);
    uint32_t rxB  = (uint32_t)lane & 7;
    uint32_t cB   = ((uint32_t)lane >> 3) & 1;

    for (int cc = 0; cc < CH; cc++) {
        if (cc + 1 < CH) cp_wait1(); else cp_wait0();
        __syncthreads();
        uint32_t stg = sb + (cc & 1) * STAGE;
        uint32_t aB  = stg + A_HI_O + rowA * 128;
        uint32_t bB  = stg + W_O + rowB * 128;

#pragma unroll
        for (int kb = 0; kb < 4; kb++) {
            uint32_t colA = (((uint32_t)(kb * 2) + cA) ^ rxA) << 4;
            uint32_t colB = (((uint32_t)(kb * 2) + cB) ^ rxB) << 4;
            uint32_t b[16];
#pragma unroll
            for (int n2 = 0; n2 < 4; n2++)
                ldm_x4(b[n2 * 4], b[n2 * 4 + 1], b[n2 * 4 + 2], b[n2 * 4 + 3],
                       bB + n2 * 2048 + colB);
            uint32_t h0[2], h1[2], h2[2], h3[2];
#pragma unroll
            for (int mi = 0; mi < 2; mi++)
                ldm_x4(h0[mi], h1[mi], h2[mi], h3[mi], aB + mi * 2048 + colA);
#pragma unroll
            for (int mi = 0; mi < 2; mi++)
#pragma unroll
                for (int n2 = 0; n2 < 4; n2++) {
                    mma16816(acc[mi][n2 * 2],     h0[mi], h1[mi], h2[mi], h3[mi],
                             b[n2 * 4],     b[n2 * 4 + 1]);
                    mma16816(acc[mi][n2 * 2 + 1], h0[mi], h1[mi], h2[mi], h3[mi],
                             b[n2 * 4 + 2], b[n2 * 4 + 3]);
                }
#pragma unroll
            for (int mi = 0; mi < 2; mi++)
                ldm_x4(h0[mi], h1[mi], h2[mi], h3[mi],
                       aB + (A_LO_O - A_HI_O) + mi * 2048 + colA);
#pragma unroll
            for (int mi = 0; mi < 2; mi++)
#pragma unroll
                for (int n2 = 0; n2 < 4; n2++) {
                    mma16816(acc[mi][n2 * 2],     h0[mi], h1[mi], h2[mi], h3[mi],
                             b[n2 * 4],     b[n2 * 4 + 1]);
                    mma16816(acc[mi][n2 * 2 + 1], h0[mi], h1[mi], h2[mi], h3[mi],
                             b[n2 * 4 + 2], b[n2 * 4 + 3]);
                }
        }
        __syncthreads();
        if (cc + 2 < CH) {
            load_stage(cc & 1, cc + 2);
            if constexpr (COMPA) comp_a(cc & 1, cc + 2);
        }
    }

    // ---------- epilogue: residual + LayerNorm (+ producers) ----------
    float2* red = (float2*)smem;                  // [64][4]
    float2* mr  = (float2*)(smem + 2048);         // [64]
    float*  pps = (float*)(smem + 4096);          // [2][256] (MODE 2)

    int mcol = wn * 64 + (lane & 3) * 2;
    int r0l  = wm * 32 + (lane >> 2);

#pragma unroll
    for (int mi = 0; mi < 2; mi++) {
        float s0 = 0, q0 = 0, s1 = 0, q1 = 0;
        size_t ra = bm + r0l + mi * 16;
#pragma unroll
        for (int ni = 0; ni < 8; ni++) {
            int col = mcol + ni * 8;
            float2 x0 = *(const float2*)(g_x + ra * E_ + col);
            float2 x1 = *(const float2*)(g_x + (ra + 8) * E_ + col);
            float bcx = bias[col], bcy = bias[col + 1];
            float v0 = acc[mi][ni][0] + bcx + x0.x;
            float v1 = acc[mi][ni][1] + bcy + x0.y;
            float v2 = acc[mi][ni][2] + bcx + x1.x;
            float v3 = acc[mi][ni][3] + bcy + x1.y;
            acc[mi][ni][0] = v0; acc[mi][ni][1] = v1;
            acc[mi][ni][2] = v2; acc[mi][ni][3] = v3;
            s0 += v0 + v1; q0 += v0 * v0 + v1 * v1;
            s1 += v2 + v3; q1 += v2 * v2 + v3 * v3;
        }
#pragma unroll
        for (int o = 1; o <= 2; o <<= 1) {
            s0 += __shfl_xor_sync(0xffffffffu, s0, o);
            q0 += __shfl_xor_sync(0xffffffffu, q0, o);
            s1 += __shfl_xor_sync(0xffffffffu, s1, o);
            q1 += __shfl_xor_sync(0xffffffffu, q1, o);
        }
        if ((lane & 3) == 0) {
            int rl = r0l + mi * 16;
            red[rl * 4 + wn] = make_float2(s0, q0);
            red[(rl + 8) * 4 + wn] = make_float2(s1, q1);
        }
    }
    __syncthreads();
    if (tid < 64) {
        float s = 0, q = 0;
#pragma unroll
        for (int j = 0; j < 4; j++) { float2 t = red[tid * 4 + j]; s += t.x; q += t.y; }
        float mean = s * (1.0f / E_);
        float var  = q * (1.0f / E_) - mean * mean;
        mr[tid] = make_float2(mean, rsqrtf(var + 1e-5f));
    }
    __syncthreads();

    float cf0 = 0.f, cf1 = 0.f;
    if constexpr (MODE == 0) {
        int c = (lane & 3) * 2;
        cf0 = cosf(fTh[c]); cf1 = cosf(fTh[c + 1]);
    }
    float ps[8][2];
    if constexpr (MODE == 2) {
#pragma unroll
        for (int ni = 0; ni < 8; ni++) { ps[ni][0] = 0.f; ps[ni][1] = 0.f; }
    }

#pragma unroll
    for (int mi = 0; mi < 2; mi++) {
        int rl = r0l + mi * 16;
        float2 m0 = mr[rl], m1 = mr[rl + 8];
        size_t ra = bm + rl;
#pragma unroll
        for (int ni = 0; ni < 8; ni++) {
            int col = mcol + ni * 8;
            float gx = lnG[col], gy = lnG[col + 1];
            float bx = lnB[col], by = lnB[col + 1];
            float o0 = (acc[mi][ni][0] - m0.x) * m0.y * gx + bx;
            float o1 = (acc[mi][ni][1] - m0.x) * m0.y * gy + by;
            float o2 = (acc[mi][ni][2] - m1.x) * m1.y * gx + bx;
            float o3 = (acc[mi][ni][3] - m1.x) * m1.y * gy + by;
            if constexpr (MODE != 2) {
                *(float2*)(g_x + ra * E_ + col) = make_float2(o0, o1);
                *(float2*)(g_x + (ra + 8) * E_ + col) = make_float2(o2, o3);
            }
            if constexpr (MODE == 0) {
                if (wn == 0 && ni == 0) {
                    int c = (lane & 3) * 2;
                    g_q[ra * 8 + c]           = cosf(o0) * cf0;
                    g_q[ra * 8 + c + 1]       = cosf(o1) * cf1;
                    g_q[(ra + 8) * 8 + c]     = cosf(o2) * cf0;
                    g_q[(ra + 8) * 8 + c + 1] = cosf(o3) * cf1;
                }
            }
            if constexpr (MODE == 1) {
                float t0 = thN[col & 63], t1 = thN[(col + 1) & 63];
                float a0 = cosf(o0 + t0), a1 = cosf(o1 + t1);
                float a2 = cosf(o2 + t0), a3 = cosf(o3 + t1);
                __half p0 = __float2half_rn(a0), p1 = __float2half_rn(a1);
                __half p2 = __float2half_rn(a2), p3 = __float2half_rn(a3);
                *(__half2*)(g_ahi + ra * E_ + col) = __halves2half2(p0, p1);
                *(__half2*)(g_ahi + (ra + 8) * E_ + col) = __halves2half2(p2, p3);
                *(__half2*)(g_alo + ra * E_ + col) =
                    __halves2half2(__float2half_rn(a0 - __half2float(p0)),
                                   __float2half_rn(a1 - __half2float(p1)));
                *(__half2*)(g_alo + (ra + 8) * E_ + col) =
                    __halves2half2(__float2half_rn(a2 - __half2float(p2)),
                                   __float2half_rn(a3 - __half2float(p3)));
            }
            if constexpr (MODE == 2) {
                ps[ni][0] += o0 + o2;
                ps[ni][1] += o1 + o3;
            }
        }
    }

    if constexpr (MODE == 2) {
#pragma unroll
        for (int ni = 0; ni < 8; ni++)
#pragma unroll
            for (int o = 4; o <= 16; o <<= 1) {
                ps[ni][0] += __shfl_xor_sync(0xffffffffu, ps[ni][0], o);
                ps[ni][1] += __shfl_xor_sync(0xffffffffu, ps[ni][1], o);
            }
        if (lane < 4) {
#pragma unroll
            for (int ni = 0; ni < 8; ni++) {
                pps[wm * 256 + mcol + ni * 8]     = ps[ni][0];
                pps[wm * 256 + mcol + ni * 8 + 1] = ps[ni][1];
            }
        }
        __syncthreads();
        if (tid < 256) g_pp[blockIdx.x * 256 + tid] = pps[tid] + pps[256 + tid];
    }
}

// ---------------- classifier -------------------------------------------------
__global__ void k_cls(const float* __restrict__ w, const float* __restrict__ cb,
                      float* __restrict__ out) {
    __shared__ float sh[16];
    int b = blockIdx.x, e = threadIdx.x;
    float p = 0.f;
#pragma unroll 8
    for (int j = 0; j < 32; j++) p += g_pp[(b * 32 + j) * E_ + e];
    p *= (1.0f / (float)S_);
    float s0 = p * w[e * 2], s1 = p * w[e * 2 + 1];
    for (int o = 16; o > 0; o >>= 1) {
        s0 += __shfl_xor_sync(0xffffffffu, s0, o);
        s1 += __shfl_xor_sync(0xffffffffu, s1, o);
    }
    int wi = e >> 5;
    if ((e & 31) == 0) { sh[wi * 2] = s0; sh[wi * 2 + 1] = s1; }
    __syncthreads();
    if (e == 0) {
        float t0 = 0, t1 = 0;
#pragma unroll
        for (int j = 0; j < 8; j++) { t0 += sh[j * 2]; t1 += sh[j * 2 + 1]; }
        out[b * 2]     = t0 + cb[0];
        out[b * 2 + 1] = t1 + cb[1];
    }
}

// ---------------- host launcher ----------------------------------------------
extern "C" void kernel_launch(void* const* d_in, const int* in_sizes, int n_in,
                              void* d_out, int out_size) {
    const int*   tokens     = (const int*)d_in[0];
    const float* embed      = (const float*)d_in[1];
    const float* attn_theta = (const float*)d_in[2];
    const float* combine_w  = (const float*)d_in[3];
    const float* combine_b  = (const float*)d_in[4];
    const float* ffn_theta  = (const float*)d_in[5];
    const float* lin1_w     = (const float*)d_in[6];
    const float* lin1_b     = (const float*)d_in[7];
    const float* lin2_w     = (const float*)d_in[8];
    const float* lin2_b     = (const float*)d_in[9];
    const float* ln1_g      = (const float*)d_in[10];
    const float* ln1_b      = (const float*)d_in[11];
    const float* ln2_g      = (const float*)d_in[12];
    const float* ln2_b      = (const float*)d_in[13];
    const float* cls_w      = (const float*)d_in[14];
    const float* cls_b      = (const float*)d_in[15];
    float* out = (float*)d_out;

    __half *ahi, *alo, *wh;
    float *qp;
    cudaGetSymbolAddress((void**)&ahi, g_ahi);
    cudaGetSymbolAddress((void**)&alo, g_alo);
    cudaGetSymbolAddress((void**)&wh,  g_wh);
    cudaGetSymbolAddress((void**)&qp,  g_q);

    cudaFuncSetAttribute(k_gf<256, 0, false>, cudaFuncAttributeMaxDynamicSharedMemorySize, SME_ATT);
    cudaFuncSetAttribute(k_gf<512, 1, true>,  cudaFuncAttributeMaxDynamicSharedMemorySize, SME_FFN);
    cudaFuncSetAttribute(k_gf<512, 2, true>,  cudaFuncAttributeMaxDynamicSharedMemorySize, SME_FFN);

    k_embed<<<M_, 256>>>(tokens, embed, attn_theta);
    k_convw<<<dim3(256, 4), 256>>>(combine_w, lin2_w);

    // layer 0
    k_gf<256, 0, false><<<M_ / 64, 256, SME_ATT>>>(
        ahi, alo, wh + 0 * 131072, combine_b + 0 * E_,
        ln1_g + 0 * E_, ln1_b + 0 * E_, nullptr,
        ffn_theta + 0 * NQ_, nullptr, nullptr, nullptr);
    k_gf<512, 1, true><<<M_ / 64, 256, SME_FFN>>>(
        nullptr, nullptr, wh + 2 * 131072, lin2_b + 0 * E_,
        ln2_g + 0 * E_, ln2_b + 0 * E_, attn_theta + 1 * 64,
        nullptr, qp, lin1_w + 0 * NQ_ * FFN_, lin1_b + 0 * FFN_);
    // layer 1
    k_gf<256, 0, false><<<M_ / 64, 256, SME_ATT>>>(
        ahi, alo, wh + 1 * 131072, combine_b + 1 * E_,
        ln1_g + 1 * E_, ln1_b + 1 * E_, nullptr,
        ffn_theta + 1 * NQ_, nullptr, nullptr, nullptr);
    k_gf<512, 2, true><<<M_ / 64, 256, SME_FFN>>>(
        nullptr, nullptr, wh + 3 * 131072, lin2_b + 1 * E_,
        ln2_g + 1 * E_, ln2_b + 1 * E_, nullptr,
        nullptr, qp, lin1_w + 1 * NQ_ * FFN_, lin1_b + 1 * FFN_);

    k_cls<<<B_, 256>>>(cls_w, cls_b, out);
}